// round 3
// baseline (speedup 1.0000x reference)
#include <cuda_runtime.h>
#include <cstdint>

#define T_STEPS 512
#define BATCH   64
#define HID     512
#define NCOLS   2048   // 4*HID

#define G_CTAS  128
#define TPB     512
#define UPC     4      // hidden units per CTA

// ---------------- scratch (no allocations allowed) ----------------
__device__ float g_h[2][HID * BATCH];                       // [buf][k][b]
__device__ float g_Zx[(size_t)T_STEPS * NCOLS * BATCH];     // [t][col][b]  (256 MB)
__device__ unsigned int g_bar;
__device__ int g_is_u8;
__device__ unsigned char g_r[T_STEPS * BATCH];              // normalized resets

// smem layout for recurrent kernel (floats):
//  sh_w  [512*16]     Wh slice      (32 KB)
//  sh_red[16*1040]    partials      (~65 KB)
//  sh_z  [1024]       combined z
//  sh_nh [256]        new h staging
//  sh_r  [64]         reset flags
#define SH_W_F   (512 * 16)
#define SH_RED_F (16 * 1040)
#define SMEM_BYTES ((SH_W_F + SH_RED_F + 1024 + 256) * 4 + 64)

__device__ __forceinline__ int red_idx(int ww, int out) {
    int f4 = out >> 2;
    int sw = f4 ^ ((f4 >> 5) & 6);   // spread cg across banks
    return ww * 1040 + sw * 4 + (out & 3);
}

__device__ __forceinline__ float sigf(float x) {
    return 1.0f / (1.0f + __expf(-x));
}

// ---------------- zero kernel: reset flags ----------------
__global__ void zero_kernel() {
    g_bar = 0u;
    g_is_u8 = 0;
}

// ---------------- detect resets dtype ----------------
// If resets is int32 (bool upcast), every byte at offset %4 != 0 is zero.
// If resets is 1-byte bool, ~50% of those bytes are nonzero. Scan the first
// 32768 bytes (in-bounds under either interpretation: int32 -> 128KB buffer,
// uint8 -> 32KB buffer).
__global__ void detect_kernel(const unsigned char* __restrict__ r) {
    __shared__ int any;
    if (threadIdx.x == 0) any = 0;
    __syncthreads();
    int i = blockIdx.x * blockDim.x + threadIdx.x;   // 0..8191 -> uchar4
    uchar4 v = ((const uchar4*)r)[i];
    if (v.y | v.z | v.w) any = 1;
    __syncthreads();
    if (threadIdx.x == 0 && any) atomicExch(&g_is_u8, 1);
}

// ---------------- init: expand resets, transpose h0 into g_h[0] ----------------
__global__ void init_kernel(const unsigned char* __restrict__ resets,
                            const float* __restrict__ h0) {
    int i = blockIdx.x * blockDim.x + threadIdx.x;   // 0..32767
    bool u8 = (g_is_u8 != 0);
    unsigned char rv;
    if (u8) rv = (resets[i] != 0);
    else    rv = (((const int*)resets)[i] != 0);
    g_r[i] = rv;
    int k = i >> 6;
    int b = i & 63;
    g_h[0][i] = h0[b * HID + k];
}

// ---------------- pre-GEMM: Zx[t][col][b] = sum_k xs[t][b][k]*Wi[k][col] + bias[col] ----------------
__global__ __launch_bounds__(256, 4) void pregemm_kernel(
    const float* __restrict__ xs, const float* __restrict__ Wi,
    const float* __restrict__ bias)
{
    __shared__ float Xs[64][64];    // [k][b]
    __shared__ float Ws[64][128];   // [k][c]
    int t   = blockIdx.y;
    int cb  = blockIdx.x * 128;
    int tid = threadIdx.x;
    int tb = tid & 15, tc = tid >> 4;
    int b0 = tb * 4,   c0 = tc * 8;

    float acc[8][4];
#pragma unroll
    for (int c = 0; c < 8; c++)
#pragma unroll
        for (int b = 0; b < 4; b++) acc[c][b] = 0.0f;

    const float* xbase = xs + (size_t)t * BATCH * HID;

    for (int kc = 0; kc < HID; kc += 64) {
        {   // X tile, transposed to [k][b]
            int b = tid & 63, kq = tid >> 6;   // kq 0..3
#pragma unroll
            for (int i = 0; i < 4; i++) {
                float4 v = *(const float4*)(xbase + b * HID + kc + kq * 16 + i * 4);
                int k = kq * 16 + i * 4;
                Xs[k + 0][b] = v.x; Xs[k + 1][b] = v.y;
                Xs[k + 2][b] = v.z; Xs[k + 3][b] = v.w;
            }
        }
#pragma unroll
        for (int i = 0; i < 8; i++) {  // W tile (direct copy)
            int lin4 = tid + i * 256;
            int k = lin4 >> 5, c4 = (lin4 & 31) * 4;
            *(float4*)&Ws[k][c4] =
                *(const float4*)(Wi + (size_t)(kc + k) * NCOLS + cb + c4);
        }
        __syncthreads();
#pragma unroll 8
        for (int k = 0; k < 64; k++) {
            float4 xv = *(const float4*)&Xs[k][b0];
            float4 wa = *(const float4*)&Ws[k][c0];
            float4 wb = *(const float4*)&Ws[k][c0 + 4];
            float xr[4] = {xv.x, xv.y, xv.z, xv.w};
            float wr[8] = {wa.x, wa.y, wa.z, wa.w, wb.x, wb.y, wb.z, wb.w};
#pragma unroll
            for (int c = 0; c < 8; c++)
#pragma unroll
                for (int b = 0; b < 4; b++)
                    acc[c][b] = fmaf(wr[c], xr[b], acc[c][b]);
        }
        __syncthreads();
    }

    float* zbase = g_Zx + (size_t)t * NCOLS * BATCH;
#pragma unroll
    for (int c = 0; c < 8; c++) {
        float bv = bias[cb + c0 + c];
        float4 v = make_float4(acc[c][0] + bv, acc[c][1] + bv,
                               acc[c][2] + bv, acc[c][3] + bv);
        *(float4*)(zbase + (size_t)(cb + c0 + c) * BATCH + b0) = v;
    }
}

// ---------------- persistent recurrent kernel ----------------
__global__ __launch_bounds__(TPB, 1) void lstm_kernel(
    const float* __restrict__ c0,
    const float* __restrict__ Wh,
    float* __restrict__ ys)
{
    extern __shared__ char smem_raw[];
    float* sh_w   = (float*)smem_raw;            // [512][16]
    float* sh_red = sh_w + SH_W_F;               // [16][1040]
    float* sh_z   = sh_red + SH_RED_F;           // [1024]  (col16*64 + b)
    float* sh_nh  = sh_z + 1024;                 // [4][64]
    unsigned char* sh_r = (unsigned char*)(sh_nh + 256);  // [64]

    int cta = blockIdx.x;
    int tid = threadIdx.x;
    int w = tid >> 5, l = tid & 31;
    int bg = l & 7, cg = l >> 3;     // cg == gate index, lane's 4 cols = 4 units of that gate

    // Wh slice: sh_w[k*16 + gi*4 + j] = Wh[k][gi*512 + cta*4 + j]
    for (int i = tid; i < 512 * 16; i += TPB) {
        int k = i >> 4, c = i & 15;
        int gi = c >> 2, j = c & 3;
        sh_w[i] = Wh[(size_t)k * NCOLS + gi * HID + cta * UPC + j];
    }

    // persistent c state in registers (threads 0..255: one (unit j, batch b) each)
    int gj = tid >> 6, gb = tid & 63;
    float creg = 0.0f;
    if (tid < 256) creg = c0[gb * HID + cta * UPC + gj];

    __syncthreads();

    const int kbase = w * 32;

    for (int t = 0; t < T_STEPS; t++) {
        const float* hsrc = g_h[t & 1];
        if (tid < 64) sh_r[tid] = g_r[t * BATCH + tid];

        float acc[4][8];
#pragma unroll
        for (int c = 0; c < 4; c++)
#pragma unroll
            for (int b = 0; b < 8; b++) acc[c][b] = 0.0f;

        const float* hp = hsrc + kbase * BATCH + bg * 8;
        const float* wp = sh_w + kbase * 16 + cg * 4;
#pragma unroll 8
        for (int k = 0; k < 32; k++) {
            float4 ha = __ldcg((const float4*)(hp + k * BATCH));
            float4 hb = __ldcg((const float4*)(hp + k * BATCH + 4));
            float4 wv = *(const float4*)(wp + k * 16);
            float hr[8] = {ha.x, ha.y, ha.z, ha.w, hb.x, hb.y, hb.z, hb.w};
            float wr[4] = {wv.x, wv.y, wv.z, wv.w};
#pragma unroll
            for (int c = 0; c < 4; c++)
#pragma unroll
                for (int b = 0; b < 8; b++)
                    acc[c][b] = fmaf(hr[b], wr[c], acc[c][b]);
        }

        // partials -> smem (swizzled to spread banks)
#pragma unroll
        for (int c = 0; c < 4; c++) {
            int outb = (cg * 4 + c) * 64 + bg * 8;
            *(float4*)&sh_red[red_idx(w, outb)] =
                make_float4(acc[c][0], acc[c][1], acc[c][2], acc[c][3]);
            *(float4*)&sh_red[red_idx(w, outb + 4)] =
                make_float4(acc[c][4], acc[c][5], acc[c][6], acc[c][7]);
        }
        __syncthreads();

        // cross-warp reduce + Zx add + reset mask -> sh_z
#pragma unroll
        for (int rep = 0; rep < 2; rep++) {
            int out = tid + rep * 512;
            float s = 0.0f;
#pragma unroll
            for (int ww = 0; ww < 16; ww++) s += sh_red[red_idx(ww, out)];
            int b = out & 63, c16 = out >> 6;
            int gi = c16 >> 2, j = c16 & 3;
            float zx = g_Zx[((size_t)t * NCOLS + gi * HID + cta * UPC + j) * BATCH + b];
            sh_z[out] = zx + (sh_r[b] ? 0.0f : s);
        }
        __syncthreads();

        // gates + state update
        if (tid < 256) {
            float zi = sh_z[(0 + gj) * 64 + gb];
            float zf = sh_z[(4 + gj) * 64 + gb];
            float zg = sh_z[(8 + gj) * 64 + gb];
            float zo = sh_z[(12 + gj) * 64 + gb];
            float ci = sh_r[gb] ? 0.0f : creg;
            float iv = sigf(zi);
            float fv = sigf(zf);
            float gv = tanhf(zg);
            float ov = sigf(zo);
            float nc = fv * ci + iv * gv;
            float nh = ov * tanhf(nc);
            nc = fminf(1.0f, fmaxf(-1.0f, nc));
            nh = fminf(1.0f, fmaxf(-1.0f, nh));
            creg = nc;
            __stcg(&g_h[(t + 1) & 1][(cta * UPC + gj) * BATCH + gb], nh);
            sh_nh[gj * 64 + gb] = nh;
        }
        __threadfence();   // make g_h writes GPU-visible before the barrier arrive
        __syncthreads();

        // coalesced-ish ys write: one float4 (4 units) per batch row
        if (tid < 64) {
            float4 v = make_float4(sh_nh[tid], sh_nh[64 + tid],
                                   sh_nh[128 + tid], sh_nh[192 + tid]);
            *(float4*)(ys + ((size_t)t * BATCH + tid) * HID + cta * UPC) = v;
        }

        // grid barrier (monotonic counter; all 128 CTAs are co-resident)
        if (tid == 0) {
            atomicAdd(&g_bar, 1u);
            unsigned target = (unsigned)(t + 1) * (unsigned)G_CTAS;
            while (*((volatile unsigned*)&g_bar) < target) { }
            __threadfence();
        }
        __syncthreads();
    }
}

// ---------------- launch ----------------
extern "C" void kernel_launch(void* const* d_in, const int* in_sizes, int n_in,
                              void* d_out, int out_size) {
    (void)in_sizes; (void)n_in; (void)out_size;
    const float*         xs     = (const float*)d_in[0];
    const unsigned char* resets = (const unsigned char*)d_in[1];
    const float*         c0     = (const float*)d_in[2];
    const float*         h0     = (const float*)d_in[3];
    const float*         Wi     = (const float*)d_in[4];
    const float*         Wh     = (const float*)d_in[5];
    const float*         bias   = (const float*)d_in[6];
    float*               ys     = (float*)d_out;

    cudaFuncSetAttribute(lstm_kernel,
                         cudaFuncAttributeMaxDynamicSharedMemorySize, SMEM_BYTES);

    zero_kernel<<<1, 1>>>();
    detect_kernel<<<32, 256>>>(resets);
    init_kernel<<<64, 512>>>(resets, h0);

    dim3 g1(NCOLS / 128, T_STEPS);
    pregemm_kernel<<<g1, 256>>>(xs, Wi, bias);

    lstm_kernel<<<G_CTAS, TPB, SMEM_BYTES>>>(c0, Wh, ys);
}

// round 4
// speedup vs baseline: 1.0010x; 1.0010x over previous
#include <cuda_runtime.h>
#include <cstdint>

#define T_STEPS 512
#define BATCH   64
#define HID     512
#define NCOLS   2048   // 4*HID

#define G_CTAS  128
#define TPB     512
#define UPC     4      // hidden units per CTA

// ---------------- scratch (no allocations allowed) ----------------
__device__ float g_h[2][HID * BATCH];                       // [buf][k][b]
__device__ float g_Zx[(size_t)T_STEPS * NCOLS * BATCH];     // [t][col][b]  (256 MB)
__device__ unsigned int g_bar;
__device__ int g_is_u8;
__device__ unsigned char g_r[T_STEPS * BATCH];              // normalized resets

// smem layout for recurrent kernel (floats):
//  sh_w  [512*16]     Wh slice      (32 KB)
//  sh_red[16*1040]    partials      (~65 KB)
//  sh_z  [1024]       combined z
//  sh_nh [256]        new h staging
//  sh_r  [64]         reset flags
#define SH_W_F   (512 * 16)
#define SH_RED_F (16 * 1040)
#define SMEM_BYTES ((SH_W_F + SH_RED_F + 1024 + 256) * 4 + 64)

__device__ __forceinline__ int red_idx(int ww, int out) {
    int f4 = out >> 2;
    int sw = f4 ^ ((f4 >> 5) & 6);   // spread cg across banks
    return ww * 1040 + sw * 4 + (out & 3);
}

__device__ __forceinline__ float sigf(float x) {
    return 1.0f / (1.0f + __expf(-x));
}

// ---------------- zero kernel: reset flags ----------------
__global__ void zero_kernel() {
    g_bar = 0u;
    g_is_u8 = 0;
}

// ---------------- detect resets dtype ----------------
// If resets is int32 (bool upcast), every byte at offset %4 != 0 is zero.
// If resets is 1-byte bool, ~50% of those bytes are nonzero. Scan the first
// 32768 bytes (in-bounds under either interpretation: int32 -> 128KB buffer,
// uint8 -> 32KB buffer).
__global__ void detect_kernel(const unsigned char* __restrict__ r) {
    __shared__ int any;
    if (threadIdx.x == 0) any = 0;
    __syncthreads();
    int i = blockIdx.x * blockDim.x + threadIdx.x;   // 0..8191 -> uchar4
    uchar4 v = ((const uchar4*)r)[i];
    if (v.y | v.z | v.w) any = 1;
    __syncthreads();
    if (threadIdx.x == 0 && any) atomicExch(&g_is_u8, 1);
}

// ---------------- init: expand resets, transpose h0 into g_h[0] ----------------
__global__ void init_kernel(const unsigned char* __restrict__ resets,
                            const float* __restrict__ h0) {
    int i = blockIdx.x * blockDim.x + threadIdx.x;   // 0..32767
    bool u8 = (g_is_u8 != 0);
    unsigned char rv;
    if (u8) rv = (resets[i] != 0);
    else    rv = (((const int*)resets)[i] != 0);
    g_r[i] = rv;
    int k = i >> 6;
    int b = i & 63;
    g_h[0][i] = h0[b * HID + k];
}

// ---------------- pre-GEMM: Zx[t][col][b] = sum_k xs[t][b][k]*Wi[k][col] + bias[col] ----------------
__global__ __launch_bounds__(256, 4) void pregemm_kernel(
    const float* __restrict__ xs, const float* __restrict__ Wi,
    const float* __restrict__ bias)
{
    __shared__ float Xs[64][64];    // [k][b]
    __shared__ float Ws[64][128];   // [k][c]
    int t   = blockIdx.y;
    int cb  = blockIdx.x * 128;
    int tid = threadIdx.x;
    int tb = tid & 15, tc = tid >> 4;
    int b0 = tb * 4,   c0 = tc * 8;

    float acc[8][4];
#pragma unroll
    for (int c = 0; c < 8; c++)
#pragma unroll
        for (int b = 0; b < 4; b++) acc[c][b] = 0.0f;

    const float* xbase = xs + (size_t)t * BATCH * HID;

    for (int kc = 0; kc < HID; kc += 64) {
        {   // X tile, transposed to [k][b]
            int b = tid & 63, kq = tid >> 6;   // kq 0..3
#pragma unroll
            for (int i = 0; i < 4; i++) {
                float4 v = *(const float4*)(xbase + b * HID + kc + kq * 16 + i * 4);
                int k = kq * 16 + i * 4;
                Xs[k + 0][b] = v.x; Xs[k + 1][b] = v.y;
                Xs[k + 2][b] = v.z; Xs[k + 3][b] = v.w;
            }
        }
#pragma unroll
        for (int i = 0; i < 8; i++) {  // W tile (direct copy)
            int lin4 = tid + i * 256;
            int k = lin4 >> 5, c4 = (lin4 & 31) * 4;
            *(float4*)&Ws[k][c4] =
                *(const float4*)(Wi + (size_t)(kc + k) * NCOLS + cb + c4);
        }
        __syncthreads();
#pragma unroll 8
        for (int k = 0; k < 64; k++) {
            float4 xv = *(const float4*)&Xs[k][b0];
            float4 wa = *(const float4*)&Ws[k][c0];
            float4 wb = *(const float4*)&Ws[k][c0 + 4];
            float xr[4] = {xv.x, xv.y, xv.z, xv.w};
            float wr[8] = {wa.x, wa.y, wa.z, wa.w, wb.x, wb.y, wb.z, wb.w};
#pragma unroll
            for (int c = 0; c < 8; c++)
#pragma unroll
                for (int b = 0; b < 4; b++)
                    acc[c][b] = fmaf(wr[c], xr[b], acc[c][b]);
        }
        __syncthreads();
    }

    float* zbase = g_Zx + (size_t)t * NCOLS * BATCH;
#pragma unroll
    for (int c = 0; c < 8; c++) {
        float bv = bias[cb + c0 + c];
        float4 v = make_float4(acc[c][0] + bv, acc[c][1] + bv,
                               acc[c][2] + bv, acc[c][3] + bv);
        *(float4*)(zbase + (size_t)(cb + c0 + c) * BATCH + b0) = v;
    }
}

// ---------------- persistent recurrent kernel ----------------
__global__ __launch_bounds__(TPB, 1) void lstm_kernel(
    const float* __restrict__ c0,
    const float* __restrict__ Wh,
    float* __restrict__ ys)
{
    extern __shared__ char smem_raw[];
    float* sh_w   = (float*)smem_raw;            // [512][16]
    float* sh_red = sh_w + SH_W_F;               // [16][1040]
    float* sh_z   = sh_red + SH_RED_F;           // [1024]  (col16*64 + b)
    float* sh_nh  = sh_z + 1024;                 // [4][64]
    unsigned char* sh_r = (unsigned char*)(sh_nh + 256);  // [64]

    int cta = blockIdx.x;
    int tid = threadIdx.x;
    int w = tid >> 5, l = tid & 31;
    int bg = l & 7, cg = l >> 3;     // cg == gate index, lane's 4 cols = 4 units of that gate

    // Wh slice: sh_w[k*16 + gi*4 + j] = Wh[k][gi*512 + cta*4 + j]
    for (int i = tid; i < 512 * 16; i += TPB) {
        int k = i >> 4, c = i & 15;
        int gi = c >> 2, j = c & 3;
        sh_w[i] = Wh[(size_t)k * NCOLS + gi * HID + cta * UPC + j];
    }

    // persistent c state in registers (threads 0..255: one (unit j, batch b) each)
    int gj = tid >> 6, gb = tid & 63;
    float creg = 0.0f;
    if (tid < 256) creg = c0[gb * HID + cta * UPC + gj];

    __syncthreads();

    const int kbase = w * 32;

    for (int t = 0; t < T_STEPS; t++) {
        const float* hsrc = g_h[t & 1];
        if (tid < 64) sh_r[tid] = g_r[t * BATCH + tid];

        float acc[4][8];
#pragma unroll
        for (int c = 0; c < 4; c++)
#pragma unroll
            for (int b = 0; b < 8; b++) acc[c][b] = 0.0f;

        const float* hp = hsrc + kbase * BATCH + bg * 8;
        const float* wp = sh_w + kbase * 16 + cg * 4;
#pragma unroll 8
        for (int k = 0; k < 32; k++) {
            float4 ha = __ldcg((const float4*)(hp + k * BATCH));
            float4 hb = __ldcg((const float4*)(hp + k * BATCH + 4));
            float4 wv = *(const float4*)(wp + k * 16);
            float hr[8] = {ha.x, ha.y, ha.z, ha.w, hb.x, hb.y, hb.z, hb.w};
            float wr[4] = {wv.x, wv.y, wv.z, wv.w};
#pragma unroll
            for (int c = 0; c < 4; c++)
#pragma unroll
                for (int b = 0; b < 8; b++)
                    acc[c][b] = fmaf(hr[b], wr[c], acc[c][b]);
        }

        // partials -> smem (swizzled to spread banks)
#pragma unroll
        for (int c = 0; c < 4; c++) {
            int outb = (cg * 4 + c) * 64 + bg * 8;
            *(float4*)&sh_red[red_idx(w, outb)] =
                make_float4(acc[c][0], acc[c][1], acc[c][2], acc[c][3]);
            *(float4*)&sh_red[red_idx(w, outb + 4)] =
                make_float4(acc[c][4], acc[c][5], acc[c][6], acc[c][7]);
        }
        __syncthreads();

        // cross-warp reduce + Zx add + reset mask -> sh_z
#pragma unroll
        for (int rep = 0; rep < 2; rep++) {
            int out = tid + rep * 512;
            float s = 0.0f;
#pragma unroll
            for (int ww = 0; ww < 16; ww++) s += sh_red[red_idx(ww, out)];
            int b = out & 63, c16 = out >> 6;
            int gi = c16 >> 2, j = c16 & 3;
            float zx = g_Zx[((size_t)t * NCOLS + gi * HID + cta * UPC + j) * BATCH + b];
            sh_z[out] = zx + (sh_r[b] ? 0.0f : s);
        }
        __syncthreads();

        // gates + state update
        if (tid < 256) {
            float zi = sh_z[(0 + gj) * 64 + gb];
            float zf = sh_z[(4 + gj) * 64 + gb];
            float zg = sh_z[(8 + gj) * 64 + gb];
            float zo = sh_z[(12 + gj) * 64 + gb];
            float ci = sh_r[gb] ? 0.0f : creg;
            float iv = sigf(zi);
            float fv = sigf(zf);
            float gv = tanhf(zg);
            float ov = sigf(zo);
            float nc = fv * ci + iv * gv;
            float nh = ov * tanhf(nc);
            nc = fminf(1.0f, fmaxf(-1.0f, nc));
            nh = fminf(1.0f, fmaxf(-1.0f, nh));
            creg = nc;
            __stcg(&g_h[(t + 1) & 1][(cta * UPC + gj) * BATCH + gb], nh);
            sh_nh[gj * 64 + gb] = nh;
        }
        __threadfence();   // make g_h writes GPU-visible before the barrier arrive
        __syncthreads();

        // coalesced-ish ys write: one float4 (4 units) per batch row
        if (tid < 64) {
            float4 v = make_float4(sh_nh[tid], sh_nh[64 + tid],
                                   sh_nh[128 + tid], sh_nh[192 + tid]);
            *(float4*)(ys + ((size_t)t * BATCH + tid) * HID + cta * UPC) = v;
        }

        // grid barrier (monotonic counter; all 128 CTAs are co-resident)
        if (tid == 0) {
            atomicAdd(&g_bar, 1u);
            unsigned target = (unsigned)(t + 1) * (unsigned)G_CTAS;
            while (*((volatile unsigned*)&g_bar) < target) { }
            __threadfence();
        }
        __syncthreads();
    }
}

// ---------------- launch ----------------
extern "C" void kernel_launch(void* const* d_in, const int* in_sizes, int n_in,
                              void* d_out, int out_size) {
    (void)in_sizes; (void)n_in; (void)out_size;
    const float*         xs     = (const float*)d_in[0];
    const unsigned char* resets = (const unsigned char*)d_in[1];
    const float*         c0     = (const float*)d_in[2];
    const float*         h0     = (const float*)d_in[3];
    const float*         Wi     = (const float*)d_in[4];
    const float*         Wh     = (const float*)d_in[5];
    const float*         bias   = (const float*)d_in[6];
    float*               ys     = (float*)d_out;

    cudaFuncSetAttribute(lstm_kernel,
                         cudaFuncAttributeMaxDynamicSharedMemorySize, SMEM_BYTES);

    zero_kernel<<<1, 1>>>();
    detect_kernel<<<32, 256>>>(resets);
    init_kernel<<<64, 512>>>(resets, h0);

    dim3 g1(NCOLS / 128, T_STEPS);
    pregemm_kernel<<<g1, 256>>>(xs, Wi, bias);

    lstm_kernel<<<G_CTAS, TPB, SMEM_BYTES>>>(c0, Wh, ys);
}

// round 7
// speedup vs baseline: 1.0021x; 1.0011x over previous
#include <cuda_runtime.h>
#include <cuda_fp16.h>
#include <cstdint>

#define T_STEPS 512
#define BATCH   64
#define HID     512
#define NCOLS   2048

#define L_CTAS  64
#define L_TPB   256

// ---- lstm smem byte offsets ----
#define SA_HI 0                      // A hi: 32 rows x 1024B
#define SA_LO 32768
#define SB_HI 65536                  // B hi: 64 rows x 1024B
#define SB_LO 131072
#define SPART 196608                 // 4 slabs of 32x68 fp32
#define SLAB  8704
#define SR    (SPART + 4 * SLAB)     // 231424: reset bytes
#define SMEM_TOTAL (SR + 64)         // 231488 <= 232448

// ---------------- scratch ----------------
__device__ __align__(16) __half g_hb[BATCH * HID];    // h hi  [b][k]
__device__ __align__(16) __half g_hbl[BATCH * HID];   // h lo  [b][k]
__device__ __align__(16) float g_Zx[(size_t)T_STEPS * NCOLS * BATCH]; // [t][prow][b]
__device__ unsigned int g_bar;
__device__ int g_is_u8;
__device__ unsigned char g_r[T_STEPS * BATCH];

// ---------------- FMA-only activations ----------------
__device__ __forceinline__ float rcp_nr(float v) {
    float y = __int_as_float(0x7EF311C3 - __float_as_int(v));
    y = y * (2.0f - v * y);
    y = y * (2.0f - v * y);
    y = y * (2.0f - v * y);
    return y;
}
__device__ __forceinline__ float sig_fast(float x) {
    float s = fminf(fmaxf(-x * 1.4426950408889634f, -30.0f), 30.0f);
    float fl = floorf(s);
    float f = s - fl;
    float p = 1.5403530393381609e-4f;
    p = fmaf(p, f, 1.3333558146428443e-3f);
    p = fmaf(p, f, 9.6181291076284770e-3f);
    p = fmaf(p, f, 5.5504108664821580e-2f);
    p = fmaf(p, f, 2.4022650695910070e-1f);
    p = fmaf(p, f, 6.9314718055994530e-1f);
    p = fmaf(p, f, 1.0f);
    float u = __int_as_float(__float_as_int(p) + (((int)fl) << 23));  // 2^s
    return rcp_nr(1.0f + u);
}
__device__ __forceinline__ float tanh_fast(float x) {
    return fmaf(2.0f, sig_fast(2.0f * x), -1.0f);
}

// swizzled tile offsets (bytes): pitch 1024B per row, 16B-granule xor
__device__ __forceinline__ uint32_t aoff(int m, int k) {
    return (uint32_t)m * 1024u + (((uint32_t)k * 2u) ^ (((uint32_t)m & 7u) << 4));
}
__device__ __forceinline__ uint32_t boff(int n, int k) {
    return (uint32_t)n * 1024u + (((uint32_t)k * 2u) ^ (((uint32_t)n & 7u) << 4));
}

#define MMA16816(d, a, b0v, b1v) \
    asm volatile("mma.sync.aligned.m16n8k16.row.col.f32.f16.f16.f32 " \
        "{%0,%1,%2,%3}, {%4,%5,%6,%7}, {%8,%9}, {%0,%1,%2,%3};" \
        : "+f"((d)[0]), "+f"((d)[1]), "+f"((d)[2]), "+f"((d)[3]) \
        : "r"((a)[0]), "r"((a)[1]), "r"((a)[2]), "r"((a)[3]), "r"(b0v), "r"(b1v))

// ---------------- setup kernels ----------------
__global__ void zero_kernel() { g_bar = 0u; g_is_u8 = 0; }

__global__ void detect_kernel(const unsigned char* __restrict__ r) {
    __shared__ int any;
    if (threadIdx.x == 0) any = 0;
    __syncthreads();
    int i = blockIdx.x * blockDim.x + threadIdx.x;
    uchar4 v = ((const uchar4*)r)[i];
    if (v.y | v.z | v.w) any = 1;
    __syncthreads();
    if (threadIdx.x == 0 && any) atomicExch(&g_is_u8, 1);
}

__global__ void init_kernel(const unsigned char* __restrict__ resets,
                            const float* __restrict__ h0) {
    int i = blockIdx.x * blockDim.x + threadIdx.x;   // 0..32767
    g_r[i] = g_is_u8 ? (resets[i] != 0) : (((const int*)resets)[i] != 0);
    float v = h0[i];                                  // [b][k] natural
    __half hi = __float2half_rn(v);
    __half lo = __float2half_rn(v - __half2float(hi));
    g_hb[i] = hi;
    g_hbl[i] = lo;
}

// ---------------- pre-GEMM: Zx[t][prow][b], prow = 4*unit+gate ----------------
__global__ __launch_bounds__(256, 4) void pregemm_kernel(
    const float* __restrict__ xs, const float* __restrict__ Wi,
    const float* __restrict__ bias)
{
    __shared__ float Xs[64][64];
    __shared__ float Ws[64][128];
    int t = blockIdx.y, cb = blockIdx.x * 128, tid = threadIdx.x;
    int b0 = (tid & 15) * 4, c0 = (tid >> 4) * 8;

    float acc[8][4];
#pragma unroll
    for (int c = 0; c < 8; c++)
#pragma unroll
        for (int b = 0; b < 4; b++) acc[c][b] = 0.0f;

    const float* xbase = xs + (size_t)t * BATCH * HID;
    for (int kc = 0; kc < HID; kc += 64) {
        {
            int b = tid & 63, kq = tid >> 6;
#pragma unroll
            for (int i = 0; i < 4; i++) {
                float4 v = *(const float4*)(xbase + b * HID + kc + kq * 16 + i * 4);
                int k = kq * 16 + i * 4;
                Xs[k][b] = v.x; Xs[k + 1][b] = v.y; Xs[k + 2][b] = v.z; Xs[k + 3][b] = v.w;
            }
        }
#pragma unroll
        for (int i = 0; i < 8; i++) {
            int lin4 = tid + i * 256;
            int k = lin4 >> 5, c4 = (lin4 & 31) * 4;
            *(float4*)&Ws[k][c4] = *(const float4*)(Wi + (size_t)(kc + k) * NCOLS + cb + c4);
        }
        __syncthreads();
#pragma unroll 8
        for (int k = 0; k < 64; k++) {
            float4 xv = *(const float4*)&Xs[k][b0];
            float4 wa = *(const float4*)&Ws[k][c0];
            float4 wb = *(const float4*)&Ws[k][c0 + 4];
            float xr[4] = {xv.x, xv.y, xv.z, xv.w};
            float wr[8] = {wa.x, wa.y, wa.z, wa.w, wb.x, wb.y, wb.z, wb.w};
#pragma unroll
            for (int c = 0; c < 8; c++)
#pragma unroll
                for (int b = 0; b < 4; b++) acc[c][b] = fmaf(wr[c], xr[b], acc[c][b]);
        }
        __syncthreads();
    }
#pragma unroll
    for (int c = 0; c < 8; c++) {
        int col = cb + c0 + c;
        int prow = (col & 511) * 4 + (col >> 9);
        float bv = bias[col];
        float4 v = make_float4(acc[c][0] + bv, acc[c][1] + bv, acc[c][2] + bv, acc[c][3] + bv);
        *(float4*)(g_Zx + ((size_t)t * NCOLS + prow) * BATCH + b0) = v;
    }
}

// ---------------- persistent HMMA recurrent kernel ----------------
__global__ __launch_bounds__(L_TPB, 1) void lstm_kernel(
    const float* __restrict__ c0, const float* __restrict__ Wh,
    float* __restrict__ ys)
{
    extern __shared__ char smem[];
    unsigned char* sr = (unsigned char*)(smem + SR);
    float* spart = (float*)(smem + SPART);
    float* sz = spart;                 // alias slab 0 (written after reads)
    float* snh = spart + SLAB / 4;     // alias slab 1

    int cta = blockIdx.x;
    int tid = threadIdx.x, wid = tid >> 5, lane = tid & 31;
    int g = lane >> 2, tg = lane & 3;

    // ---- prologue: Wh slice -> fp16 hi/lo in smem ----
    // A[m][k] = Wh[k][col], col = gate*512 + unit; prow = cta*32+m; gate=prow&3, unit=prow>>2
    for (int it = 0; it < 64; it++) {
        int idx = tid + it * 256;                  // 0..16383
        int m = idx >> 9, k = idx & 511;
        int prow = cta * 32 + m;
        float w = Wh[(size_t)k * NCOLS + (prow & 3) * 512 + (prow >> 2)];
        __half hi = __float2half_rn(w);
        __half lo = __float2half_rn(w - __half2float(hi));
        uint32_t o = aoff(m, k);
        *(__half*)(smem + SA_HI + o) = hi;
        *(__half*)(smem + SA_LO + o) = lo;
    }

    // c state: 2 per thread: idx q*256+tid -> u = idx>>6, b = idx&63
    float creg[2];
#pragma unroll
    for (int q = 0; q < 2; q++) {
        int idx = tid + q * 256;
        creg[q] = c0[(idx & 63) * HID + cta * 8 + (idx >> 6)];
    }
    __syncthreads();

    for (int t = 0; t < T_STEPS; t++) {
        // ---- phase 1: load h -> B hi/lo smem ----
        if (tid < 64) sr[tid] = g_r[t * BATCH + tid];
#pragma unroll 4
        for (int it = 0; it < 16; it++) {
            int idx = tid + it * 256;              // chunk: n = idx>>6, ch = idx&63
            int n = idx >> 6, ch = idx & 63;
            uint32_t o = (uint32_t)n * 1024u + (((uint32_t)ch * 16u) ^ (((uint32_t)n & 7u) << 4));
            uint4 vh = __ldcg(((const uint4*)g_hb) + idx);
            uint4 vl = __ldcg(((const uint4*)g_hbl) + idx);
            *(uint4*)(smem + SB_HI + o) = vh;
            *(uint4*)(smem + SB_LO + o) = vl;
        }
        __syncthreads();

        // ---- phase 2: HMMA (warps 0-3), Zx prefetch (warps 4-7) ----
        if (wid < 4) {
            float d[2][8][4];
#pragma unroll
            for (int mt = 0; mt < 2; mt++)
#pragma unroll
                for (int nt = 0; nt < 8; nt++)
#pragma unroll
                    for (int e = 0; e < 4; e++) d[mt][nt][e] = 0.0f;

#pragma unroll 1
            for (int pass = 0; pass < 3; pass++) {
                const char* As = smem + ((pass == 2) ? SA_LO : SA_HI);
                const char* Bs = smem + ((pass == 1) ? SB_LO : SB_HI);
#pragma unroll 1
                for (int kc = 0; kc < 8; kc++) {
                    int k = wid * 128 + kc * 16 + 2 * tg;
                    uint32_t a[2][4];
#pragma unroll
                    for (int mt = 0; mt < 2; mt++) {
                        int m0 = mt * 16 + g;
                        a[mt][0] = *(const uint32_t*)(As + aoff(m0, k));
                        a[mt][1] = *(const uint32_t*)(As + aoff(m0 + 8, k));
                        a[mt][2] = *(const uint32_t*)(As + aoff(m0, k + 8));
                        a[mt][3] = *(const uint32_t*)(As + aoff(m0 + 8, k + 8));
                    }
#pragma unroll
                    for (int nt = 0; nt < 8; nt++) {
                        int n = nt * 8 + g;
                        uint32_t b0 = *(const uint32_t*)(Bs + boff(n, k));
                        uint32_t b1 = *(const uint32_t*)(Bs + boff(n, k + 8));
                        MMA16816(d[0][nt], a[0], b0, b1);
                        MMA16816(d[1][nt], a[1], b0, b1);
                    }
                }
            }
            // store partials: slab[wid], row*68 + col
            float* sp = spart + wid * (SLAB / 4);
#pragma unroll
            for (int mt = 0; mt < 2; mt++)
#pragma unroll
                for (int nt = 0; nt < 8; nt++) {
                    int r0 = mt * 16 + g, cc = nt * 8 + 2 * tg;
                    *(float2*)&sp[r0 * 68 + cc] = make_float2(d[mt][nt][0], d[mt][nt][1]);
                    *(float2*)&sp[(r0 + 8) * 68 + cc] = make_float2(d[mt][nt][2], d[mt][nt][3]);
                }
        } else {
            // prefetch this CTA's Zx slice (8KB = 64 lines) into L2
            int li = tid - 128;
            if (li < 64) {
                const char* zp = (const char*)(g_Zx + ((size_t)t * NCOLS + cta * 32) * BATCH) + li * 128;
                asm volatile("prefetch.global.L2 [%0];" :: "l"(zp));
            }
        }
        __syncthreads();

        // ---- phase 3: reduce partials + Zx + reset mask -> sz ----
        {
            int m = tid >> 3, bb = (tid & 7) * 8;
            const float* zxp = g_Zx + ((size_t)t * NCOLS + cta * 32 + m) * BATCH + bb;
            float4 zx0 = *(const float4*)(zxp);
            float4 zx1 = *(const float4*)(zxp + 4);
            float s[8] = {0, 0, 0, 0, 0, 0, 0, 0};
#pragma unroll
            for (int w = 0; w < 4; w++) {
                const float* sp = spart + w * (SLAB / 4) + m * 68 + bb;
                float4 p0 = *(const float4*)(sp);
                float4 p1 = *(const float4*)(sp + 4);
                s[0] += p0.x; s[1] += p0.y; s[2] += p0.z; s[3] += p0.w;
                s[4] += p1.x; s[5] += p1.y; s[6] += p1.z; s[7] += p1.w;
            }
            float zr[8] = {zx0.x, zx0.y, zx0.z, zx0.w, zx1.x, zx1.y, zx1.z, zx1.w};
            float o[8];
#pragma unroll
            for (int j = 0; j < 8; j++)
                o[j] = zr[j] + (sr[bb + j] ? 0.0f : s[j]);
            *(float4*)&sz[m * 68 + bb]     = make_float4(o[0], o[1], o[2], o[3]);
            *(float4*)&sz[m * 68 + bb + 4] = make_float4(o[4], o[5], o[6], o[7]);
        }
        __syncthreads();

        // ---- phase 4: gates (FMA-only activations) ----
#pragma unroll
        for (int q = 0; q < 2; q++) {
            int idx = tid + q * 256;
            int u = idx >> 6, b = idx & 63;
            float zi = sz[(4 * u + 0) * 68 + b];
            float zf = sz[(4 * u + 1) * 68 + b];
            float zg = sz[(4 * u + 2) * 68 + b];
            float zo = sz[(4 * u + 3) * 68 + b];
            float ci = sr[b] ? 0.0f : creg[q];
            float iv = sig_fast(zi);
            float fv = sig_fast(zf);
            float gv = tanh_fast(zg);
            float ov = sig_fast(zo);
            float nc = fmaf(fv, ci, iv * gv);
            float nh = ov * tanh_fast(nc);
            nc = fminf(1.0f, fmaxf(-1.0f, nc));
            nh = fminf(1.0f, fmaxf(-1.0f, nh));
            creg[q] = nc;
            snh[u * 64 + b] = nh;
        }
        __syncthreads();

        // ---- phase 5: write ys + global h (fp16 hi/lo) ----
        if (tid < 128) {
            int b = tid >> 1, h4 = (tid & 1) * 4;
            float v0 = snh[(h4 + 0) * 64 + b];
            float v1 = snh[(h4 + 1) * 64 + b];
            float v2 = snh[(h4 + 2) * 64 + b];
            float v3 = snh[(h4 + 3) * 64 + b];
            *(float4*)(ys + ((size_t)t * BATCH + b) * HID + cta * 8 + h4) =
                make_float4(v0, v1, v2, v3);
            __half h0v = __float2half_rn(v0), h1v = __float2half_rn(v1);
            __half h2v = __float2half_rn(v2), h3v = __float2half_rn(v3);
            __half l0 = __float2half_rn(v0 - __half2float(h0v));
            __half l1 = __float2half_rn(v1 - __half2float(h1v));
            __half l2 = __float2half_rn(v2 - __half2float(h2v));
            __half l3 = __float2half_rn(v3 - __half2float(h3v));
            uint2 ph, pl;
            ph.x = (uint32_t)__half_as_ushort(h0v) | ((uint32_t)__half_as_ushort(h1v) << 16);
            ph.y = (uint32_t)__half_as_ushort(h2v) | ((uint32_t)__half_as_ushort(h3v) << 16);
            pl.x = (uint32_t)__half_as_ushort(l0) | ((uint32_t)__half_as_ushort(l1) << 16);
            pl.y = (uint32_t)__half_as_ushort(l2) | ((uint32_t)__half_as_ushort(l3) << 16);
            __stcg((uint2*)(g_hb + b * HID + cta * 8 + h4), ph);
            __stcg((uint2*)(g_hbl + b * HID + cta * 8 + h4), pl);
        }
        __threadfence();
        __syncthreads();

        // ---- grid barrier (64 co-resident CTAs) ----
        if (tid == 0) {
            atomicAdd(&g_bar, 1u);
            unsigned target = (unsigned)(t + 1) * (unsigned)L_CTAS;
            while (*((volatile unsigned*)&g_bar) < target) { }
            __threadfence();
        }
        __syncthreads();
    }
}

// ---------------- launch ----------------
extern "C" void kernel_launch(void* const* d_in, const int* in_sizes, int n_in,
                              void* d_out, int out_size) {
    (void)in_sizes; (void)n_in; (void)out_size;
    const float*         xs     = (const float*)d_in[0];
    const unsigned char* resets = (const unsigned char*)d_in[1];
    const float*         c0     = (const float*)d_in[2];
    const float*         h0     = (const float*)d_in[3];
    const float*         Wi     = (const float*)d_in[4];
    const float*         Wh     = (const float*)d_in[5];
    const float*         bias   = (const float*)d_in[6];
    float*               ys     = (float*)d_out;

    cudaFuncSetAttribute(lstm_kernel,
                         cudaFuncAttributeMaxDynamicSharedMemorySize, SMEM_TOTAL);

    zero_kernel<<<1, 1>>>();
    detect_kernel<<<32, 256>>>(resets);
    init_kernel<<<64, 512>>>(resets, h0);

    dim3 g1(NCOLS / 128, T_STEPS);
    pregemm_kernel<<<g1, 256>>>(xs, Wi, bias);

    lstm_kernel<<<L_CTAS, L_TPB, SMEM_TOTAL>>>(c0, Wh, ys);
}

// round 9
// speedup vs baseline: 1.7424x; 1.7389x over previous
#include <cuda_runtime.h>
#include <cuda_fp16.h>
#include <cstdint>

#define T_STEPS 512
#define BATCH   64
#define HID     512
#define NCOLS   2048

#define L_CTAS  128
#define L_TPB   256

// ---- lstm smem byte offsets ----
#define SA_HI 0                       // A hi: 16 rows x 1024B
#define SA_LO 16384                   // A lo
#define SB    32768                   // B (h fp16): 64 rows x 1024B
#define SPART 98304                   // 4 slabs of 16x68 fp32
#define SLABF (16 * 68)
#define SR    (98304 + 4 * SLABF * 4) // 115712
#define SMEM_TOTAL (SR + 64)

// ---------------- scratch ----------------
__device__ __align__(16) __half g_hb[BATCH * HID];                     // h fp16 [b][k]
__device__ __align__(16) float g_Zx[(size_t)T_STEPS * NCOLS * BATCH];  // [t][prow][b]
__device__ unsigned int g_bar;
__device__ int g_is_u8;
__device__ unsigned char g_r[T_STEPS * BATCH];

// ---------------- FMA-only activations ----------------
__device__ __forceinline__ float rcp_nr(float v) {
    float y = __int_as_float(0x7EF311C3 - __float_as_int(v));
    y = y * (2.0f - v * y);
    y = y * (2.0f - v * y);
    y = y * (2.0f - v * y);
    return y;
}
__device__ __forceinline__ float sig_fast(float x) {
    float s = fminf(fmaxf(-x * 1.4426950408889634f, -30.0f), 30.0f);
    float fl = floorf(s);
    float f = s - fl;
    float p = 1.5403530393381609e-4f;
    p = fmaf(p, f, 1.3333558146428443e-3f);
    p = fmaf(p, f, 9.6181291076284770e-3f);
    p = fmaf(p, f, 5.5504108664821580e-2f);
    p = fmaf(p, f, 2.4022650695910070e-1f);
    p = fmaf(p, f, 6.9314718055994530e-1f);
    p = fmaf(p, f, 1.0f);
    float uu = __int_as_float(__float_as_int(p) + (((int)fl) << 23));
    return rcp_nr(1.0f + uu);
}
__device__ __forceinline__ float tanh_fast(float x) {
    return fmaf(2.0f, sig_fast(2.0f * x), -1.0f);
}

// swizzled tile offsets (bytes): 1024B rows, 16B-granule xor
__device__ __forceinline__ uint32_t aoff(int m, int k) {
    return (uint32_t)m * 1024u + (((uint32_t)k * 2u) ^ (((uint32_t)m & 7u) << 4));
}
__device__ __forceinline__ uint32_t boff(int n, int k) {
    return (uint32_t)n * 1024u + (((uint32_t)k * 2u) ^ (((uint32_t)n & 7u) << 4));
}

#define MMA16816(d, a, b0v, b1v) \
    asm volatile("mma.sync.aligned.m16n8k16.row.col.f32.f16.f16.f32 " \
        "{%0,%1,%2,%3}, {%4,%5,%6,%7}, {%8,%9}, {%0,%1,%2,%3};" \
        : "+f"((d)[0]), "+f"((d)[1]), "+f"((d)[2]), "+f"((d)[3]) \
        : "r"((a)[0]), "r"((a)[1]), "r"((a)[2]), "r"((a)[3]), "r"(b0v), "r"(b1v))

// ---------------- setup kernels ----------------
__global__ void zero_kernel() { g_bar = 0u; g_is_u8 = 0; }

__global__ void detect_kernel(const unsigned char* __restrict__ r) {
    __shared__ int any;
    if (threadIdx.x == 0) any = 0;
    __syncthreads();
    int i = blockIdx.x * blockDim.x + threadIdx.x;
    uchar4 v = ((const uchar4*)r)[i];
    if (v.y | v.z | v.w) any = 1;
    __syncthreads();
    if (threadIdx.x == 0 && any) atomicExch(&g_is_u8, 1);
}

__global__ void init_kernel(const unsigned char* __restrict__ resets,
                            const float* __restrict__ h0) {
    int i = blockIdx.x * blockDim.x + threadIdx.x;   // 0..32767
    g_r[i] = g_is_u8 ? (resets[i] != 0) : (((const int*)resets)[i] != 0);
    g_hb[i] = __float2half_rn(h0[i]);                 // [b][k]
}

// ---------------- pre-GEMM: Zx[t][prow][b], prow = 4*unit+gate ----------------
__global__ __launch_bounds__(256, 4) void pregemm_kernel(
    const float* __restrict__ xs, const float* __restrict__ Wi,
    const float* __restrict__ bias)
{
    __shared__ float Xs[64][64];
    __shared__ float Ws[64][128];
    int t = blockIdx.y, cb = blockIdx.x * 128, tid = threadIdx.x;
    int b0 = (tid & 15) * 4, c0 = (tid >> 4) * 8;

    float acc[8][4];
#pragma unroll
    for (int c = 0; c < 8; c++)
#pragma unroll
        for (int b = 0; b < 4; b++) acc[c][b] = 0.0f;

    const float* xbase = xs + (size_t)t * BATCH * HID;
    for (int kc = 0; kc < HID; kc += 64) {
        {
            int b = tid & 63, kq = tid >> 6;
#pragma unroll
            for (int i = 0; i < 4; i++) {
                float4 v = *(const float4*)(xbase + b * HID + kc + kq * 16 + i * 4);
                int k = kq * 16 + i * 4;
                Xs[k][b] = v.x; Xs[k + 1][b] = v.y; Xs[k + 2][b] = v.z; Xs[k + 3][b] = v.w;
            }
        }
#pragma unroll
        for (int i = 0; i < 8; i++) {
            int lin4 = tid + i * 256;
            int k = lin4 >> 5, c4 = (lin4 & 31) * 4;
            *(float4*)&Ws[k][c4] = *(const float4*)(Wi + (size_t)(kc + k) * NCOLS + cb + c4);
        }
        __syncthreads();
#pragma unroll 8
        for (int k = 0; k < 64; k++) {
            float4 xv = *(const float4*)&Xs[k][b0];
            float4 wa = *(const float4*)&Ws[k][c0];
            float4 wb = *(const float4*)&Ws[k][c0 + 4];
            float xr[4] = {xv.x, xv.y, xv.z, xv.w};
            float wr[8] = {wa.x, wa.y, wa.z, wa.w, wb.x, wb.y, wb.z, wb.w};
#pragma unroll
            for (int c = 0; c < 8; c++)
#pragma unroll
                for (int b = 0; b < 4; b++) acc[c][b] = fmaf(wr[c], xr[b], acc[c][b]);
        }
        __syncthreads();
    }
#pragma unroll
    for (int c = 0; c < 8; c++) {
        int col = cb + c0 + c;
        int prow = (col & 511) * 4 + (col >> 9);
        float bv = bias[col];
        float4 v = make_float4(acc[c][0] + bv, acc[c][1] + bv, acc[c][2] + bv, acc[c][3] + bv);
        *(float4*)(g_Zx + ((size_t)t * NCOLS + prow) * BATCH + b0) = v;
    }
}

// ---------------- persistent HMMA recurrent kernel (128 CTAs, M=16) ----------------
__global__ __launch_bounds__(L_TPB, 1) void lstm_kernel(
    const float* __restrict__ c0, const float* __restrict__ Wh,
    float* __restrict__ ys)
{
    extern __shared__ char smem[];
    float* spart = (float*)(smem + SPART);
    float* sz = spart;                 // alias slab 0
    float* snh = spart + SLABF;        // alias slab 1
    unsigned char* sr = (unsigned char*)(smem + SR);

    int cta = blockIdx.x;
    int tid = threadIdx.x, wid = tid >> 5, lane = tid & 31;
    int g = lane >> 2, tg = lane & 3;

    // ---- prologue: Wh slice -> fp16 hi/lo in smem ----
    // A[m][k] = Wh[k][gate*512 + unit], gate = m&3, unit = cta*4 + (m>>2)
    for (int it = 0; it < 32; it++) {
        int idx = tid + it * 256;                  // 0..8191
        int m = idx >> 9, k = idx & 511;
        float w = Wh[(size_t)k * NCOLS + (m & 3) * 512 + cta * 4 + (m >> 2)];
        __half hi = __float2half_rn(w);
        __half lo = __float2half_rn(w - __half2float(hi));
        uint32_t o = aoff(m, k);
        *(__half*)(smem + SA_HI + o) = hi;
        *(__half*)(smem + SA_LO + o) = lo;
    }

    // c state: one (u, b) per thread
    int u = tid >> 6, b = tid & 63;
    float creg = c0[b * HID + cta * 4 + u];
    __syncthreads();

    for (int t = 0; t < T_STEPS; t++) {
        if (tid < 64) sr[tid] = g_r[t * BATCH + tid];

        // ---- p1a: all warps load B half0 (k 0..255) ----
#pragma unroll
        for (int it = 0; it < 8; it++) {
            int idx = tid + it * 256;              // 2048 16B-chunks/half
            int n = idx >> 5, ch = idx & 31;
            uint32_t o = (uint32_t)n * 1024u + (((uint32_t)ch * 16u) ^ (((uint32_t)n & 7u) << 4));
            uint4 v = __ldcg((const uint4*)(g_hb + n * HID + ch * 8));
            *(uint4*)(smem + SB + o) = v;
        }
        __syncthreads();

        float d[8][4];
        // ---- p2a: MMA half0 (warps 0-3) / load half1 (warps 4-7) ----
        if (wid < 4) {
#pragma unroll
            for (int nt = 0; nt < 8; nt++)
#pragma unroll
                for (int e = 0; e < 4; e++) d[nt][e] = 0.0f;
#pragma unroll
            for (int kc = 0; kc < 4; kc++) {
                int k = wid * 64 + kc * 16 + 2 * tg;
                uint32_t ah[4], al[4];
                ah[0] = *(const uint32_t*)(smem + SA_HI + aoff(g, k));
                ah[1] = *(const uint32_t*)(smem + SA_HI + aoff(g + 8, k));
                ah[2] = *(const uint32_t*)(smem + SA_HI + aoff(g, k + 8));
                ah[3] = *(const uint32_t*)(smem + SA_HI + aoff(g + 8, k + 8));
                al[0] = *(const uint32_t*)(smem + SA_LO + aoff(g, k));
                al[1] = *(const uint32_t*)(smem + SA_LO + aoff(g + 8, k));
                al[2] = *(const uint32_t*)(smem + SA_LO + aoff(g, k + 8));
                al[3] = *(const uint32_t*)(smem + SA_LO + aoff(g + 8, k + 8));
#pragma unroll
                for (int nt = 0; nt < 8; nt++) {
                    int n = nt * 8 + g;
                    uint32_t b0v = *(const uint32_t*)(smem + SB + boff(n, k));
                    uint32_t b1v = *(const uint32_t*)(smem + SB + boff(n, k + 8));
                    MMA16816(d[nt], ah, b0v, b1v);
                    MMA16816(d[nt], al, b0v, b1v);
                }
            }
        } else {
            int lt = tid - 128;
#pragma unroll
            for (int it = 0; it < 16; it++) {
                int idx = lt + it * 128;
                int n = idx >> 5, ch = 32 + (idx & 31);
                uint32_t o = (uint32_t)n * 1024u + (((uint32_t)ch * 16u) ^ (((uint32_t)n & 7u) << 4));
                uint4 v = __ldcg((const uint4*)(g_hb + n * HID + ch * 8));
                *(uint4*)(smem + SB + o) = v;
            }
        }
        __syncthreads();

        // ---- p2b: MMA half1 / Zx prefetch ----
        if (wid < 4) {
#pragma unroll
            for (int kc = 0; kc < 4; kc++) {
                int k = 256 + wid * 64 + kc * 16 + 2 * tg;
                uint32_t ah[4], al[4];
                ah[0] = *(const uint32_t*)(smem + SA_HI + aoff(g, k));
                ah[1] = *(const uint32_t*)(smem + SA_HI + aoff(g + 8, k));
                ah[2] = *(const uint32_t*)(smem + SA_HI + aoff(g, k + 8));
                ah[3] = *(const uint32_t*)(smem + SA_HI + aoff(g + 8, k + 8));
                al[0] = *(const uint32_t*)(smem + SA_LO + aoff(g, k));
                al[1] = *(const uint32_t*)(smem + SA_LO + aoff(g + 8, k));
                al[2] = *(const uint32_t*)(smem + SA_LO + aoff(g, k + 8));
                al[3] = *(const uint32_t*)(smem + SA_LO + aoff(g + 8, k + 8));
#pragma unroll
                for (int nt = 0; nt < 8; nt++) {
                    int n = nt * 8 + g;
                    uint32_t b0v = *(const uint32_t*)(smem + SB + boff(n, k));
                    uint32_t b1v = *(const uint32_t*)(smem + SB + boff(n, k + 8));
                    MMA16816(d[nt], ah, b0v, b1v);
                    MMA16816(d[nt], al, b0v, b1v);
                }
            }
            // store partials
            float* sp = spart + wid * SLABF;
#pragma unroll
            for (int nt = 0; nt < 8; nt++) {
                int cc = nt * 8 + 2 * tg;
                *(float2*)&sp[g * 68 + cc] = make_float2(d[nt][0], d[nt][1]);
                *(float2*)&sp[(g + 8) * 68 + cc] = make_float2(d[nt][2], d[nt][3]);
            }
        } else {
            int li = tid - 128;
            if (li < 32) {
                const char* zp = (const char*)(g_Zx + ((size_t)t * NCOLS + cta * 16) * BATCH) + li * 128;
                asm volatile("prefetch.global.L2 [%0];" :: "l"(zp));
            }
        }
        __syncthreads();

        // ---- p3: reduce 4 slabs + Zx + reset mask -> sz ----
        {
            int m = tid >> 4, bb = (tid & 15) * 4;
            float4 zx = __ldcg((const float4*)(g_Zx + ((size_t)t * NCOLS + cta * 16 + m) * BATCH + bb));
            float sx = 0.f, sy = 0.f, szv = 0.f, sw = 0.f;
#pragma unroll
            for (int w = 0; w < 4; w++) {
                float4 p = *(const float4*)&spart[w * SLABF + m * 68 + bb];
                sx += p.x; sy += p.y; szv += p.z; sw += p.w;
            }
            float o0 = zx.x + (sr[bb + 0] ? 0.f : sx);
            float o1 = zx.y + (sr[bb + 1] ? 0.f : sy);
            float o2 = zx.z + (sr[bb + 2] ? 0.f : szv);
            float o3 = zx.w + (sr[bb + 3] ? 0.f : sw);
            *(float4*)&sz[m * 68 + bb] = make_float4(o0, o1, o2, o3);
        }
        __syncthreads();

        // ---- p4: gates ----
        {
            float zi = sz[(4 * u + 0) * 68 + b];
            float zf = sz[(4 * u + 1) * 68 + b];
            float zg = sz[(4 * u + 2) * 68 + b];
            float zo = sz[(4 * u + 3) * 68 + b];
            float ci = sr[b] ? 0.0f : creg;
            float iv = sig_fast(zi), fv = sig_fast(zf);
            float gv = tanh_fast(zg), ov = sig_fast(zo);
            float nc = fmaf(fv, ci, iv * gv);
            float nh = ov * tanh_fast(nc);
            nc = fminf(1.0f, fmaxf(-1.0f, nc));
            nh = fminf(1.0f, fmaxf(-1.0f, nh));
            creg = nc;
            snh[u * 64 + b] = nh;
        }
        __syncthreads();

        // ---- p5: write ys (fp32) + h (fp16) ----
        if (tid < 64) {
            float v0 = snh[0 * 64 + tid], v1 = snh[1 * 64 + tid];
            float v2 = snh[2 * 64 + tid], v3 = snh[3 * 64 + tid];
            *(float4*)(ys + ((size_t)t * BATCH + tid) * HID + cta * 4) =
                make_float4(v0, v1, v2, v3);
            __half h0v = __float2half_rn(v0), h1v = __float2half_rn(v1);
            __half h2v = __float2half_rn(v2), h3v = __float2half_rn(v3);
            uint2 ph;
            ph.x = (uint32_t)__half_as_ushort(h0v) | ((uint32_t)__half_as_ushort(h1v) << 16);
            ph.y = (uint32_t)__half_as_ushort(h2v) | ((uint32_t)__half_as_ushort(h3v) << 16);
            __stcg((uint2*)(g_hb + tid * HID + cta * 4), ph);
        }
        __syncthreads();

        // ---- grid barrier: release-arrive + acquire-spin by tid0 only ----
        if (tid == 0) {
            unsigned tgt = (unsigned)(t + 1) * (unsigned)L_CTAS;
            asm volatile("red.release.gpu.global.add.u32 [%0], %1;"
                         :: "l"(&g_bar), "r"(1u) : "memory");
            unsigned v;
            do {
                asm volatile("ld.acquire.gpu.global.u32 %0, [%1];"
                             : "=r"(v) : "l"(&g_bar) : "memory");
            } while (v < tgt);
        }
        __syncthreads();
    }
}

// ---------------- launch ----------------
extern "C" void kernel_launch(void* const* d_in, const int* in_sizes, int n_in,
                              void* d_out, int out_size) {
    (void)in_sizes; (void)n_in; (void)out_size;
    const float*         xs     = (const float*)d_in[0];
    const unsigned char* resets = (const unsigned char*)d_in[1];
    const float*         c0     = (const float*)d_in[2];
    const float*         h0     = (const float*)d_in[3];
    const float*         Wi     = (const float*)d_in[4];
    const float*         Wh     = (const float*)d_in[5];
    const float*         bias   = (const float*)d_in[6];
    float*               ys     = (float*)d_out;

    cudaFuncSetAttribute(lstm_kernel,
                         cudaFuncAttributeMaxDynamicSharedMemorySize, SMEM_TOTAL);

    zero_kernel<<<1, 1>>>();
    detect_kernel<<<32, 256>>>(resets);
    init_kernel<<<64, 512>>>(resets, h0);

    dim3 g1(NCOLS / 128, T_STEPS);
    pregemm_kernel<<<g1, 256>>>(xs, Wi, bias);

    lstm_kernel<<<L_CTAS, L_TPB, SMEM_TOTAL>>>(c0, Wh, ys);
}

// round 11
// speedup vs baseline: 2.4424x; 1.4017x over previous
#include <cuda_runtime.h>
#include <cuda_fp16.h>
#include <cstdint>

#define T_STEPS 512
#define BATCH   64
#define HID     512
#define NCOLS   2048

#define L_CTAS  128
#define L_TPB   256

// ---- lstm smem byte offsets ----
#define SA_HI 0                       // A hi: 16 rows x 1024B
#define SA_LO 16384                   // A lo
#define SB    32768                   // B (h fp16): 64 rows x 1024B
#define SPART 98304                   // 4 slabs of 16x68 fp32
#define SLABF (16 * 68)
#define SR    (98304 + 4 * SLABF * 4) // 115712
#define SMEM_TOTAL (SR + 64)

// ---- pregemm smem byte offsets (256B-pitch tiles) ----
#define PA_HI 0                       // 128 rows x 256B
#define PA_LO 32768
#define PB    65536                   // 64 rows x 256B
#define PSMEM 81920

// ---------------- scratch ----------------
__device__ __align__(16) __half g_hb[BATCH * HID];                     // h fp16 [b][k]
__device__ __align__(16) float g_Zx[(size_t)T_STEPS * NCOLS * BATCH];  // [t][prow][b]
__device__ __align__(16) __half g_wih[NCOLS * HID];                    // WiT hi [col][k]
__device__ __align__(16) __half g_wil[NCOLS * HID];                    // WiT lo [col][k]
__device__ __align__(16) __half g_xh[(size_t)T_STEPS * BATCH * HID];   // xs fp16 [t][b][k]
__device__ unsigned int g_bar;
__device__ int g_is_u8;
__device__ unsigned char g_r[T_STEPS * BATCH];

// ---------------- FMA-only activations ----------------
__device__ __forceinline__ float rcp_nr(float v) {
    float y = __int_as_float(0x7EF311C3 - __float_as_int(v));
    y = y * (2.0f - v * y);
    y = y * (2.0f - v * y);
    y = y * (2.0f - v * y);
    return y;
}
__device__ __forceinline__ float sig_fast(float x) {
    float s = fminf(fmaxf(-x * 1.4426950408889634f, -30.0f), 30.0f);
    float fl = floorf(s);
    float f = s - fl;
    float p = 1.5403530393381609e-4f;
    p = fmaf(p, f, 1.3333558146428443e-3f);
    p = fmaf(p, f, 9.6181291076284770e-3f);
    p = fmaf(p, f, 5.5504108664821580e-2f);
    p = fmaf(p, f, 2.4022650695910070e-1f);
    p = fmaf(p, f, 6.9314718055994530e-1f);
    p = fmaf(p, f, 1.0f);
    float uu = __int_as_float(__float_as_int(p) + (((int)fl) << 23));
    return rcp_nr(1.0f + uu);
}
__device__ __forceinline__ float tanh_fast(float x) {
    return fmaf(2.0f, sig_fast(2.0f * x), -1.0f);
}

// swizzled tile offsets (bytes)
__device__ __forceinline__ uint32_t aoff(int m, int k) {      // 1024B pitch (lstm)
    return (uint32_t)m * 1024u + (((uint32_t)k * 2u) ^ (((uint32_t)m & 7u) << 4));
}
__device__ __forceinline__ uint32_t boff(int n, int k) {
    return (uint32_t)n * 1024u + (((uint32_t)k * 2u) ^ (((uint32_t)n & 7u) << 4));
}
__device__ __forceinline__ uint32_t off256(int r, int k) {    // 256B pitch (pregemm)
    return (uint32_t)r * 256u + (((uint32_t)k * 2u) ^ (((uint32_t)r & 7u) << 4));
}

#define MMA16816(d, a, b0v, b1v) \
    asm volatile("mma.sync.aligned.m16n8k16.row.col.f32.f16.f16.f32 " \
        "{%0,%1,%2,%3}, {%4,%5,%6,%7}, {%8,%9}, {%0,%1,%2,%3};" \
        : "+f"((d)[0]), "+f"((d)[1]), "+f"((d)[2]), "+f"((d)[3]) \
        : "r"((a)[0]), "r"((a)[1]), "r"((a)[2]), "r"((a)[3]), "r"(b0v), "r"(b1v))

// ---------------- setup kernels ----------------
__global__ void zero_kernel() { g_bar = 0u; g_is_u8 = 0; }

__global__ void detect_kernel(const unsigned char* __restrict__ r) {
    __shared__ int any;
    if (threadIdx.x == 0) any = 0;
    __syncthreads();
    int i = blockIdx.x * blockDim.x + threadIdx.x;
    uchar4 v = ((const uchar4*)r)[i];
    if (v.y | v.z | v.w) any = 1;
    __syncthreads();
    if (threadIdx.x == 0 && any) atomicExch(&g_is_u8, 1);
}

__global__ void init_kernel(const unsigned char* __restrict__ resets,
                            const float* __restrict__ h0) {
    int i = blockIdx.x * blockDim.x + threadIdx.x;   // 0..32767
    g_r[i] = g_is_u8 ? (resets[i] != 0) : (((const int*)resets)[i] != 0);
    g_hb[i] = __float2half_rn(h0[i]);                 // [b][k]
}

// Wi[k][col] fp32 -> g_wih/g_wil[col][k] fp16 (tile transpose)
__global__ __launch_bounds__(256) void wi_prep_kernel(const float* __restrict__ Wi) {
    __shared__ float tile[32][33];
    int tx = threadIdx.x & 31, ty = threadIdx.x >> 5;   // 32x8
    int c0 = blockIdx.x * 32, k0 = blockIdx.y * 32;
#pragma unroll
    for (int i = 0; i < 4; i++)
        tile[ty + 8 * i][tx] = Wi[(size_t)(k0 + ty + 8 * i) * NCOLS + c0 + tx];
    __syncthreads();
#pragma unroll
    for (int i = 0; i < 4; i++) {
        int cc = ty + 8 * i, kk = tx;
        float w = tile[kk][cc];
        __half hi = __float2half_rn(w);
        __half lo = __float2half_rn(w - __half2float(hi));
        g_wih[(size_t)(c0 + cc) * HID + k0 + kk] = hi;
        g_wil[(size_t)(c0 + cc) * HID + k0 + kk] = lo;
    }
}

// xs fp32 -> g_xh fp16
__global__ __launch_bounds__(256) void x_prep_kernel(const float* __restrict__ xs) {
    int i4 = blockIdx.x * blockDim.x + threadIdx.x;   // 4 elems each
    float4 v = ((const float4*)xs)[i4];
    __half2 a = __floats2half2_rn(v.x, v.y);
    __half2 b = __floats2half2_rn(v.z, v.w);
    uint2 o;
    o.x = *(uint32_t*)&a; o.y = *(uint32_t*)&b;
    ((uint2*)g_xh)[i4] = o;
}

// ---------------- HMMA pre-GEMM: Zx[t][prow][b], prow = 4*unit+gate ----------------
__global__ __launch_bounds__(256, 2) void pregemm_hmma_kernel(
    const float* __restrict__ bias)
{
    extern __shared__ char psm[];
    int t = blockIdx.y, cb = blockIdx.x * 128;
    int tid = threadIdx.x, wid = tid >> 5, lane = tid & 31;
    int g = lane >> 2, tg = lane & 3;

    float d[8][4];
#pragma unroll
    for (int nt = 0; nt < 8; nt++)
#pragma unroll
        for (int e = 0; e < 4; e++) d[nt][e] = 0.0f;

    for (int kc = 0; kc < 4; kc++) {
        // load A hi/lo chunk: 128 rows x 128 k
#pragma unroll
        for (int it = 0; it < 8; it++) {
            int idx = tid + it * 256;
            int r = idx >> 4, ch = idx & 15;
            uint32_t o = (uint32_t)r * 256u + (((uint32_t)ch * 16u) ^ (((uint32_t)r & 7u) << 4));
            *(uint4*)(psm + PA_HI + o) =
                *(const uint4*)(g_wih + (size_t)(cb + r) * HID + kc * 128 + ch * 8);
            *(uint4*)(psm + PA_LO + o) =
                *(const uint4*)(g_wil + (size_t)(cb + r) * HID + kc * 128 + ch * 8);
        }
        // load B chunk: 64 rows x 128 k
#pragma unroll
        for (int it = 0; it < 4; it++) {
            int idx = tid + it * 256;
            int n = idx >> 4, ch = idx & 15;
            uint32_t o = (uint32_t)n * 256u + (((uint32_t)ch * 16u) ^ (((uint32_t)n & 7u) << 4));
            *(uint4*)(psm + PB + o) =
                *(const uint4*)(g_xh + ((size_t)t * BATCH + n) * HID + kc * 128 + ch * 8);
        }
        __syncthreads();

#pragma unroll
        for (int k16 = 0; k16 < 8; k16++) {
            int k = k16 * 16 + 2 * tg;
            int r0 = wid * 16 + g;
            uint32_t ah[4], al[4];
            ah[0] = *(const uint32_t*)(psm + PA_HI + off256(r0, k));
            ah[1] = *(const uint32_t*)(psm + PA_HI + off256(r0 + 8, k));
            ah[2] = *(const uint32_t*)(psm + PA_HI + off256(r0, k + 8));
            ah[3] = *(const uint32_t*)(psm + PA_HI + off256(r0 + 8, k + 8));
            al[0] = *(const uint32_t*)(psm + PA_LO + off256(r0, k));
            al[1] = *(const uint32_t*)(psm + PA_LO + off256(r0 + 8, k));
            al[2] = *(const uint32_t*)(psm + PA_LO + off256(r0, k + 8));
            al[3] = *(const uint32_t*)(psm + PA_LO + off256(r0 + 8, k + 8));
#pragma unroll
            for (int nt = 0; nt < 8; nt++) {
                int n = nt * 8 + g;
                uint32_t b0v = *(const uint32_t*)(psm + PB + off256(n, k));
                uint32_t b1v = *(const uint32_t*)(psm + PB + off256(n, k + 8));
                MMA16816(d[nt], ah, b0v, b1v);
                MMA16816(d[nt], al, b0v, b1v);
            }
        }
        __syncthreads();
    }

    // epilogue: add bias, write Zx[t][prow][b]
    {
        int r0 = wid * 16 + g;
        int col0 = cb + r0, col1 = cb + r0 + 8;
        float bv0 = bias[col0], bv1 = bias[col1];
        int prow0 = (col0 & 511) * 4 + (col0 >> 9);
        int prow1 = (col1 & 511) * 4 + (col1 >> 9);
        float* z0 = g_Zx + ((size_t)t * NCOLS + prow0) * BATCH;
        float* z1 = g_Zx + ((size_t)t * NCOLS + prow1) * BATCH;
#pragma unroll
        for (int nt = 0; nt < 8; nt++) {
            int b = nt * 8 + 2 * tg;
            *(float2*)(z0 + b) = make_float2(d[nt][0] + bv0, d[nt][1] + bv0);
            *(float2*)(z1 + b) = make_float2(d[nt][2] + bv1, d[nt][3] + bv1);
        }
    }
}

// ---------------- persistent HMMA recurrent kernel (128 CTAs, M=16) ----------------
__global__ __launch_bounds__(L_TPB, 1) void lstm_kernel(
    const float* __restrict__ c0, const float* __restrict__ Wh,
    float* __restrict__ ys)
{
    extern __shared__ char smem[];
    float* spart = (float*)(smem + SPART);
    float* sz = spart;                 // alias slab 0
    float* snh = spart + SLABF;        // alias slab 1
    unsigned char* sr = (unsigned char*)(smem + SR);

    int cta = blockIdx.x;
    int tid = threadIdx.x, wid = tid >> 5, lane = tid & 31;
    int g = lane >> 2, tg = lane & 3;

    // prologue: Wh slice -> fp16 hi/lo; A[m][k] = Wh[k][(m&3)*512 + cta*4 + (m>>2)]
    for (int it = 0; it < 32; it++) {
        int idx = tid + it * 256;
        int m = idx >> 9, k = idx & 511;
        float w = Wh[(size_t)k * NCOLS + (m & 3) * 512 + cta * 4 + (m >> 2)];
        __half hi = __float2half_rn(w);
        __half lo = __float2half_rn(w - __half2float(hi));
        uint32_t o = aoff(m, k);
        *(__half*)(smem + SA_HI + o) = hi;
        *(__half*)(smem + SA_LO + o) = lo;
    }

    int u = tid >> 6, b = tid & 63;
    float creg = c0[b * HID + cta * 4 + u];
    __syncthreads();

    for (int t = 0; t < T_STEPS; t++) {
        if (tid < 64) sr[tid] = g_r[t * BATCH + tid];

        // p1a: all warps load B half0
#pragma unroll
        for (int it = 0; it < 8; it++) {
            int idx = tid + it * 256;
            int n = idx >> 5, ch = idx & 31;
            uint32_t o = (uint32_t)n * 1024u + (((uint32_t)ch * 16u) ^ (((uint32_t)n & 7u) << 4));
            uint4 v = __ldcg((const uint4*)(g_hb + n * HID + ch * 8));
            *(uint4*)(smem + SB + o) = v;
        }
        __syncthreads();

        float d[8][4];
        // p2a: MMA half0 / load half1
        if (wid < 4) {
#pragma unroll
            for (int nt = 0; nt < 8; nt++)
#pragma unroll
                for (int e = 0; e < 4; e++) d[nt][e] = 0.0f;
#pragma unroll
            for (int kc = 0; kc < 4; kc++) {
                int k = wid * 64 + kc * 16 + 2 * tg;
                uint32_t ah[4], al[4];
                ah[0] = *(const uint32_t*)(smem + SA_HI + aoff(g, k));
                ah[1] = *(const uint32_t*)(smem + SA_HI + aoff(g + 8, k));
                ah[2] = *(const uint32_t*)(smem + SA_HI + aoff(g, k + 8));
                ah[3] = *(const uint32_t*)(smem + SA_HI + aoff(g + 8, k + 8));
                al[0] = *(const uint32_t*)(smem + SA_LO + aoff(g, k));
                al[1] = *(const uint32_t*)(smem + SA_LO + aoff(g + 8, k));
                al[2] = *(const uint32_t*)(smem + SA_LO + aoff(g, k + 8));
                al[3] = *(const uint32_t*)(smem + SA_LO + aoff(g + 8, k + 8));
#pragma unroll
                for (int nt = 0; nt < 8; nt++) {
                    int n = nt * 8 + g;
                    uint32_t b0v = *(const uint32_t*)(smem + SB + boff(n, k));
                    uint32_t b1v = *(const uint32_t*)(smem + SB + boff(n, k + 8));
                    MMA16816(d[nt], ah, b0v, b1v);
                    MMA16816(d[nt], al, b0v, b1v);
                }
            }
        } else {
            int lt = tid - 128;
#pragma unroll
            for (int it = 0; it < 16; it++) {
                int idx = lt + it * 128;
                int n = idx >> 5, ch = 32 + (idx & 31);
                uint32_t o = (uint32_t)n * 1024u + (((uint32_t)ch * 16u) ^ (((uint32_t)n & 7u) << 4));
                uint4 v = __ldcg((const uint4*)(g_hb + n * HID + ch * 8));
                *(uint4*)(smem + SB + o) = v;
            }
        }
        __syncthreads();

        // p2b: MMA half1 / Zx prefetch
        if (wid < 4) {
#pragma unroll
            for (int kc = 0; kc < 4; kc++) {
                int k = 256 + wid * 64 + kc * 16 + 2 * tg;
                uint32_t ah[4], al[4];
                ah[0] = *(const uint32_t*)(smem + SA_HI + aoff(g, k));
                ah[1] = *(const uint32_t*)(smem + SA_HI + aoff(g + 8, k));
                ah[2] = *(const uint32_t*)(smem + SA_HI + aoff(g, k + 8));
                ah[3] = *(const uint32_t*)(smem + SA_HI + aoff(g + 8, k + 8));
                al[0] = *(const uint32_t*)(smem + SA_LO + aoff(g, k));
                al[1] = *(const uint32_t*)(smem + SA_LO + aoff(g + 8, k));
                al[2] = *(const uint32_t*)(smem + SA_LO + aoff(g, k + 8));
                al[3] = *(const uint32_t*)(smem + SA_LO + aoff(g + 8, k + 8));
#pragma unroll
                for (int nt = 0; nt < 8; nt++) {
                    int n = nt * 8 + g;
                    uint32_t b0v = *(const uint32_t*)(smem + SB + boff(n, k));
                    uint32_t b1v = *(const uint32_t*)(smem + SB + boff(n, k + 8));
                    MMA16816(d[nt], ah, b0v, b1v);
                    MMA16816(d[nt], al, b0v, b1v);
                }
            }
            float* sp = spart + wid * SLABF;
#pragma unroll
            for (int nt = 0; nt < 8; nt++) {
                int cc = nt * 8 + 2 * tg;
                *(float2*)&sp[g * 68 + cc] = make_float2(d[nt][0], d[nt][1]);
                *(float2*)&sp[(g + 8) * 68 + cc] = make_float2(d[nt][2], d[nt][3]);
            }
        } else {
            int li = tid - 128;
            if (li < 32) {
                const char* zp = (const char*)(g_Zx + ((size_t)t * NCOLS + cta * 16) * BATCH) + li * 128;
                asm volatile("prefetch.global.L2 [%0];" :: "l"(zp));
            }
        }
        __syncthreads();

        // p3: reduce + Zx + reset mask
        {
            int m = tid >> 4, bb = (tid & 15) * 4;
            float4 zx = __ldcg((const float4*)(g_Zx + ((size_t)t * NCOLS + cta * 16 + m) * BATCH + bb));
            float sx = 0.f, sy = 0.f, szv = 0.f, sw = 0.f;
#pragma unroll
            for (int w = 0; w < 4; w++) {
                float4 p = *(const float4*)&spart[w * SLABF + m * 68 + bb];
                sx += p.x; sy += p.y; szv += p.z; sw += p.w;
            }
            float o0 = zx.x + (sr[bb + 0] ? 0.f : sx);
            float o1 = zx.y + (sr[bb + 1] ? 0.f : sy);
            float o2 = zx.z + (sr[bb + 2] ? 0.f : szv);
            float o3 = zx.w + (sr[bb + 3] ? 0.f : sw);
            *(float4*)&sz[m * 68 + bb] = make_float4(o0, o1, o2, o3);
        }
        __syncthreads();

        // p4: gates
        {
            float zi = sz[(4 * u + 0) * 68 + b];
            float zf = sz[(4 * u + 1) * 68 + b];
            float zg = sz[(4 * u + 2) * 68 + b];
            float zo = sz[(4 * u + 3) * 68 + b];
            float ci = sr[b] ? 0.0f : creg;
            float iv = sig_fast(zi), fv = sig_fast(zf);
            float gv = tanh_fast(zg), ov = sig_fast(zo);
            float nc = fmaf(fv, ci, iv * gv);
            float nh = ov * tanh_fast(nc);
            nc = fminf(1.0f, fmaxf(-1.0f, nc));
            nh = fminf(1.0f, fmaxf(-1.0f, nh));
            creg = nc;
            snh[u * 64 + b] = nh;
        }
        __syncthreads();

        // p5: write ys + h
        if (tid < 64) {
            float v0 = snh[0 * 64 + tid], v1 = snh[1 * 64 + tid];
            float v2 = snh[2 * 64 + tid], v3 = snh[3 * 64 + tid];
            *(float4*)(ys + ((size_t)t * BATCH + tid) * HID + cta * 4) =
                make_float4(v0, v1, v2, v3);
            __half h0v = __float2half_rn(v0), h1v = __float2half_rn(v1);
            __half h2v = __float2half_rn(v2), h3v = __float2half_rn(v3);
            uint2 ph;
            ph.x = (uint32_t)__half_as_ushort(h0v) | ((uint32_t)__half_as_ushort(h1v) << 16);
            ph.y = (uint32_t)__half_as_ushort(h2v) | ((uint32_t)__half_as_ushort(h3v) << 16);
            __stcg((uint2*)(g_hb + tid * HID + cta * 4), ph);
        }
        __syncthreads();

        // grid barrier
        if (tid == 0) {
            unsigned tgt = (unsigned)(t + 1) * (unsigned)L_CTAS;
            asm volatile("red.release.gpu.global.add.u32 [%0], %1;"
                         :: "l"(&g_bar), "r"(1u) : "memory");
            unsigned v;
            do {
                asm volatile("ld.acquire.gpu.global.u32 %0, [%1];"
                             : "=r"(v) : "l"(&g_bar) : "memory");
            } while (v < tgt);
        }
        __syncthreads();
    }
}

// ---------------- launch ----------------
extern "C" void kernel_launch(void* const* d_in, const int* in_sizes, int n_in,
                              void* d_out, int out_size) {
    (void)in_sizes; (void)n_in; (void)out_size;
    const float*         xs     = (const float*)d_in[0];
    const unsigned char* resets = (const unsigned char*)d_in[1];
    const float*         c0     = (const float*)d_in[2];
    const float*         h0     = (const float*)d_in[3];
    const float*         Wi     = (const float*)d_in[4];
    const float*         Wh     = (const float*)d_in[5];
    const float*         bias   = (const float*)d_in[6];
    float*               ys     = (float*)d_out;

    cudaFuncSetAttribute(lstm_kernel,
                         cudaFuncAttributeMaxDynamicSharedMemorySize, SMEM_TOTAL);
    cudaFuncSetAttribute(pregemm_hmma_kernel,
                         cudaFuncAttributeMaxDynamicSharedMemorySize, PSMEM);

    zero_kernel<<<1, 1>>>();
    detect_kernel<<<32, 256>>>(resets);
    init_kernel<<<64, 512>>>(resets, h0);

    dim3 gw(NCOLS / 32, HID / 32);
    wi_prep_kernel<<<gw, 256>>>(Wi);
    x_prep_kernel<<<(T_STEPS * BATCH * HID / 4) / 256, 256>>>(xs);

    dim3 g1(NCOLS / 128, T_STEPS);
    pregemm_hmma_kernel<<<g1, 256, PSMEM>>>(bias);

    lstm_kernel<<<L_CTAS, L_TPB, SMEM_TOTAL>>>(c0, Wh, ys);
}

// round 14
// speedup vs baseline: 2.5161x; 1.0302x over previous
#include <cuda_runtime.h>
#include <cuda_fp16.h>
#include <cstdint>

#define T_STEPS 512
#define BATCH   64
#define HID     512
#define NCOLS   2048

#define L_CTAS  128
#define L_TPB   256
#define NGROUP  4
#define CPG     32       // CTAs per group
#define GB      16       // batches per group

// ---- lstm smem byte offsets ----
#define SA_HI 0                        // A hi: 64 rows x 1024B
#define SA_LO 65536                    // A lo
#define SB    131072                   // B (h fp16): 16 rows x 1024B
#define SPART 147456                   // 2 slabs of 64x20 fp32 (5120B each)
#define SNH   (SPART + 10240)          // 256 floats
#define SR    (SNH + 1024)
#define SMEM_TOTAL (SR + 64)           // 158784

// ---- pregemm smem byte offsets (256B-pitch tiles) ----
#define PA_HI 0
#define PA_LO 32768
#define PB    65536
#define PSMEM 81920

// ---------------- scratch ----------------
__device__ __align__(16) __half g_hb[BATCH * HID];                     // h fp16 [b][k]
__device__ __align__(16) float g_Zx[(size_t)T_STEPS * NCOLS * BATCH];  // [t][prow][b]
__device__ __align__(16) __half g_wih[NCOLS * HID];                    // WiT hi [col][k]
__device__ __align__(16) __half g_wil[NCOLS * HID];                    // WiT lo [col][k]
__device__ __align__(16) __half g_xh[(size_t)T_STEPS * BATCH * HID];   // xs fp16 [t][b][k]
__device__ unsigned int g_barr[NGROUP * 32];                           // 128B-spaced counters
__device__ int g_is_u8;
__device__ unsigned char g_r[T_STEPS * BATCH];

// ---------------- FMA-only activations ----------------
__device__ __forceinline__ float rcp_nr(float v) {
    float y = __int_as_float(0x7EF311C3 - __float_as_int(v));
    y = y * (2.0f - v * y);
    y = y * (2.0f - v * y);
    y = y * (2.0f - v * y);
    return y;
}
__device__ __forceinline__ float sig_fast(float x) {
    float s = fminf(fmaxf(-x * 1.4426950408889634f, -30.0f), 30.0f);
    float fl = floorf(s);
    float f = s - fl;
    float p = 1.5403530393381609e-4f;
    p = fmaf(p, f, 1.3333558146428443e-3f);
    p = fmaf(p, f, 9.6181291076284770e-3f);
    p = fmaf(p, f, 5.5504108664821580e-2f);
    p = fmaf(p, f, 2.4022650695910070e-1f);
    p = fmaf(p, f, 6.9314718055994530e-1f);
    p = fmaf(p, f, 1.0f);
    float uu = __int_as_float(__float_as_int(p) + (((int)fl) << 23));
    return rcp_nr(1.0f + uu);
}
__device__ __forceinline__ float tanh_fast(float x) {
    return fmaf(2.0f, sig_fast(2.0f * x), -1.0f);
}

// swizzled tile offsets (bytes)
__device__ __forceinline__ uint32_t aoff(int m, int k) {      // 1024B pitch
    return (uint32_t)m * 1024u + (((uint32_t)k * 2u) ^ (((uint32_t)m & 7u) << 4));
}
__device__ __forceinline__ uint32_t boff(int n, int k) {
    return (uint32_t)n * 1024u + (((uint32_t)k * 2u) ^ (((uint32_t)n & 7u) << 4));
}
__device__ __forceinline__ uint32_t off256(int r, int k) {    // 256B pitch (pregemm)
    return (uint32_t)r * 256u + (((uint32_t)k * 2u) ^ (((uint32_t)r & 7u) << 4));
}

#define MMA16816(d, a, b0v, b1v) \
    asm volatile("mma.sync.aligned.m16n8k16.row.col.f32.f16.f16.f32 " \
        "{%0,%1,%2,%3}, {%4,%5,%6,%7}, {%8,%9}, {%0,%1,%2,%3};" \
        : "+f"((d)[0]), "+f"((d)[1]), "+f"((d)[2]), "+f"((d)[3]) \
        : "r"((a)[0]), "r"((a)[1]), "r"((a)[2]), "r"((a)[3]), "r"(b0v), "r"(b1v))

// ---------------- setup kernels ----------------
__global__ void zero_kernel() {
    int i = threadIdx.x;
    if (i < NGROUP * 32) g_barr[i] = 0u;
    if (i == 0) g_is_u8 = 0;
}

__global__ void detect_kernel(const unsigned char* __restrict__ r) {
    __shared__ int any;
    if (threadIdx.x == 0) any = 0;
    __syncthreads();
    int i = blockIdx.x * blockDim.x + threadIdx.x;
    uchar4 v = ((const uchar4*)r)[i];
    if (v.y | v.z | v.w) any = 1;
    __syncthreads();
    if (threadIdx.x == 0 && any) atomicExch(&g_is_u8, 1);
}

__global__ void init_kernel(const unsigned char* __restrict__ resets,
                            const float* __restrict__ h0) {
    int i = blockIdx.x * blockDim.x + threadIdx.x;   // 0..32767
    g_r[i] = g_is_u8 ? (resets[i] != 0) : (((const int*)resets)[i] != 0);
    g_hb[i] = __float2half_rn(h0[i]);                 // [b][k]
}

// Wi[k][col] fp32 -> g_wih/g_wil[col][k] fp16 (tile transpose)
__global__ __launch_bounds__(256) void wi_prep_kernel(const float* __restrict__ Wi) {
    __shared__ float tile[32][33];
    int tx = threadIdx.x & 31, ty = threadIdx.x >> 5;   // 32x8
    int c0 = blockIdx.x * 32, k0 = blockIdx.y * 32;
#pragma unroll
    for (int i = 0; i < 4; i++)
        tile[ty + 8 * i][tx] = Wi[(size_t)(k0 + ty + 8 * i) * NCOLS + c0 + tx];
    __syncthreads();
#pragma unroll
    for (int i = 0; i < 4; i++) {
        int cc = ty + 8 * i, kk = tx;
        float w = tile[kk][cc];
        __half hi = __float2half_rn(w);
        __half lo = __float2half_rn(w - __half2float(hi));
        g_wih[(size_t)(c0 + cc) * HID + k0 + kk] = hi;
        g_wil[(size_t)(c0 + cc) * HID + k0 + kk] = lo;
    }
}

// xs fp32 -> g_xh fp16
__global__ __launch_bounds__(256) void x_prep_kernel(const float* __restrict__ xs) {
    int i4 = blockIdx.x * blockDim.x + threadIdx.x;
    float4 v = ((const float4*)xs)[i4];
    __half2 a = __floats2half2_rn(v.x, v.y);
    __half2 b = __floats2half2_rn(v.z, v.w);
    uint2 o;
    o.x = *(uint32_t*)&a; o.y = *(uint32_t*)&b;
    ((uint2*)g_xh)[i4] = o;
}

// ---------------- HMMA pre-GEMM: Zx[t][prow][b], prow = 4*unit+gate ----------------
__global__ __launch_bounds__(256, 2) void pregemm_hmma_kernel(
    const float* __restrict__ bias)
{
    extern __shared__ char psm[];
    int t = blockIdx.y, cb = blockIdx.x * 128;
    int tid = threadIdx.x, wid = tid >> 5, lane = tid & 31;
    int g = lane >> 2, tg = lane & 3;

    float d[8][4];
#pragma unroll
    for (int nt = 0; nt < 8; nt++)
#pragma unroll
        for (int e = 0; e < 4; e++) d[nt][e] = 0.0f;

    for (int kc = 0; kc < 4; kc++) {
#pragma unroll
        for (int it = 0; it < 8; it++) {
            int idx = tid + it * 256;
            int r = idx >> 4, ch = idx & 15;
            uint32_t o = (uint32_t)r * 256u + (((uint32_t)ch * 16u) ^ (((uint32_t)r & 7u) << 4));
            *(uint4*)(psm + PA_HI + o) =
                *(const uint4*)(g_wih + (size_t)(cb + r) * HID + kc * 128 + ch * 8);
            *(uint4*)(psm + PA_LO + o) =
                *(const uint4*)(g_wil + (size_t)(cb + r) * HID + kc * 128 + ch * 8);
        }
#pragma unroll
        for (int it = 0; it < 4; it++) {
            int idx = tid + it * 256;
            int n = idx >> 4, ch = idx & 15;
            uint32_t o = (uint32_t)n * 256u + (((uint32_t)ch * 16u) ^ (((uint32_t)n & 7u) << 4));
            *(uint4*)(psm + PB + o) =
                *(const uint4*)(g_xh + ((size_t)t * BATCH + n) * HID + kc * 128 + ch * 8);
        }
        __syncthreads();

#pragma unroll
        for (int k16 = 0; k16 < 8; k16++) {
            int k = k16 * 16 + 2 * tg;
            int r0 = wid * 16 + g;
            uint32_t ah[4], al[4];
            ah[0] = *(const uint32_t*)(psm + PA_HI + off256(r0, k));
            ah[1] = *(const uint32_t*)(psm + PA_HI + off256(r0 + 8, k));
            ah[2] = *(const uint32_t*)(psm + PA_HI + off256(r0, k + 8));
            ah[3] = *(const uint32_t*)(psm + PA_HI + off256(r0 + 8, k + 8));
            al[0] = *(const uint32_t*)(psm + PA_LO + off256(r0, k));
            al[1] = *(const uint32_t*)(psm + PA_LO + off256(r0 + 8, k));
            al[2] = *(const uint32_t*)(psm + PA_LO + off256(r0, k + 8));
            al[3] = *(const uint32_t*)(psm + PA_LO + off256(r0 + 8, k + 8));
#pragma unroll
            for (int nt = 0; nt < 8; nt++) {
                int n = nt * 8 + g;
                uint32_t b0v = *(const uint32_t*)(psm + PB + off256(n, k));
                uint32_t b1v = *(const uint32_t*)(psm + PB + off256(n, k + 8));
                MMA16816(d[nt], ah, b0v, b1v);
                MMA16816(d[nt], al, b0v, b1v);
            }
        }
        __syncthreads();
    }

    {
        int r0 = wid * 16 + g;
        int col0 = cb + r0, col1 = cb + r0 + 8;
        float bv0 = bias[col0], bv1 = bias[col1];
        int prow0 = (col0 & 511) * 4 + (col0 >> 9);
        int prow1 = (col1 & 511) * 4 + (col1 >> 9);
        float* z0 = g_Zx + ((size_t)t * NCOLS + prow0) * BATCH;
        float* z1 = g_Zx + ((size_t)t * NCOLS + prow1) * BATCH;
#pragma unroll
        for (int nt = 0; nt < 8; nt++) {
            int b = nt * 8 + 2 * tg;
            *(float2*)(z0 + b) = make_float2(d[nt][0] + bv0, d[nt][1] + bv0);
            *(float2*)(z1 + b) = make_float2(d[nt][2] + bv1, d[nt][3] + bv1);
        }
    }
}

// ---------------- persistent HMMA recurrent kernel ----------------
// 4 independent batch-groups of 32 CTAs; CTA: M=64 z-rows x N=16 batches, K=512
__global__ __launch_bounds__(L_TPB, 1) void lstm_kernel(
    const float* __restrict__ c0, const float* __restrict__ Wh,
    float* __restrict__ ys)
{
    extern __shared__ char smem[];
    float* spf = (float*)(smem + SPART);              // 2 slabs of 64x20
    float* sz  = spf;                                  // alias slab 0 (same-cell rewrite)
    float* snh = (float*)(smem + SNH);                 // 16u x 16b
    unsigned char* sr = (unsigned char*)(smem + SR);   // 16 bytes

    int cta = blockIdx.x;
    int bg = cta >> 5;          // batch group 0..3 -> batches bg*16..+15
    int cb = cta & 31;          // z-row block: prow cb*64..+63 (units cb*16..+15)
    int tid = threadIdx.x, wid = tid >> 5, lane = tid & 31;
    int g = lane >> 2, tg = lane & 3;

    // prologue: Wh slice -> fp16 hi/lo; A[m][k] = Wh[k][(m&3)*512 + cb*16 + (m>>2)]
    for (int it = 0; it < 128; it++) {
        int idx = tid + it * 256;                     // 0..32767
        int m = idx >> 9, k = idx & 511;
        float w = Wh[(size_t)k * NCOLS + (m & 3) * 512 + cb * 16 + (m >> 2)];
        __half hi = __float2half_rn(w);
        __half lo = __float2half_rn(w - __half2float(hi));
        uint32_t o = aoff(m, k);
        *(__half*)(smem + SA_HI + o) = hi;
        *(__half*)(smem + SA_LO + o) = lo;
    }

    // c state: 1 cell per thread: u = tid>>4 (0..15), bl = tid&15
    int u = tid >> 4, bl = tid & 15;
    float creg = c0[(bg * GB + bl) * HID + cb * 16 + u];

    // MMA warp roles: kh = K half, mt = m-tile
    int kh = wid >> 2, mt = wid & 3;
    int m0 = mt * 16 + g;
    unsigned int* barp = &g_barr[bg * 32];
    __syncthreads();

    for (int t = 0; t < T_STEPS; t++) {
        if (tid < GB) sr[tid] = g_r[t * BATCH + bg * GB + tid];

        // p1: load group's h rows (16 x 1KB)
#pragma unroll
        for (int it = 0; it < 4; it++) {
            int idx = tid + it * 256;                 // 1024 chunks of 16B
            int n = idx >> 6, ch = idx & 63;
            uint32_t o = (uint32_t)n * 1024u + (((uint32_t)ch * 16u) ^ (((uint32_t)n & 7u) << 4));
            uint4 v = __ldcg((const uint4*)(g_hb + (bg * GB + n) * HID + ch * 8));
            *(uint4*)(smem + SB + o) = v;
        }
        __syncthreads();

        // p2: MMA — all 8 warps; warp (kh, mt): K in [kh*256, kh*256+256)
        {
            float d[2][4];
#pragma unroll
            for (int nt = 0; nt < 2; nt++)
#pragma unroll
                for (int e = 0; e < 4; e++) d[nt][e] = 0.0f;
#pragma unroll
            for (int k16 = 0; k16 < 16; k16++) {
                int k = kh * 256 + k16 * 16 + 2 * tg;
                uint32_t ah[4], al[4];
                ah[0] = *(const uint32_t*)(smem + SA_HI + aoff(m0, k));
                ah[1] = *(const uint32_t*)(smem + SA_HI + aoff(m0 + 8, k));
                ah[2] = *(const uint32_t*)(smem + SA_HI + aoff(m0, k + 8));
                ah[3] = *(const uint32_t*)(smem + SA_HI + aoff(m0 + 8, k + 8));
                al[0] = *(const uint32_t*)(smem + SA_LO + aoff(m0, k));
                al[1] = *(const uint32_t*)(smem + SA_LO + aoff(m0 + 8, k));
                al[2] = *(const uint32_t*)(smem + SA_LO + aoff(m0, k + 8));
                al[3] = *(const uint32_t*)(smem + SA_LO + aoff(m0 + 8, k + 8));
#pragma unroll
                for (int nt = 0; nt < 2; nt++) {
                    int n = nt * 8 + g;
                    uint32_t b0v = *(const uint32_t*)(smem + SB + boff(n, k));
                    uint32_t b1v = *(const uint32_t*)(smem + SB + boff(n, k + 8));
                    MMA16816(d[nt], ah, b0v, b1v);
                    MMA16816(d[nt], al, b0v, b1v);
                }
            }
            // partials: slab[kh], row m (pitch 20), col b
            float* sp = spf + kh * 1280;
#pragma unroll
            for (int nt = 0; nt < 2; nt++) {
                int cc = nt * 8 + 2 * tg;
                *(float2*)&sp[(m0) * 20 + cc]     = make_float2(d[nt][0], d[nt][1]);
                *(float2*)&sp[(m0 + 8) * 20 + cc] = make_float2(d[nt][2], d[nt][3]);
            }
        }
        __syncthreads();

        // p3: reduce 2 slabs + Zx + reset mask -> sz (same-cell rewrite of slab0)
        {
            int m = tid >> 2, b4 = (tid & 3) * 4;
            float4 zx = __ldcg((const float4*)(g_Zx +
                ((size_t)t * NCOLS + cb * 64 + m) * BATCH + bg * GB + b4));
            float4 p0 = *(const float4*)&spf[m * 20 + b4];
            float4 p1 = *(const float4*)&spf[1280 + m * 20 + b4];
            float o0 = zx.x + (sr[b4 + 0] ? 0.f : (p0.x + p1.x));
            float o1 = zx.y + (sr[b4 + 1] ? 0.f : (p0.y + p1.y));
            float o2 = zx.z + (sr[b4 + 2] ? 0.f : (p0.z + p1.z));
            float o3 = zx.w + (sr[b4 + 3] ? 0.f : (p0.w + p1.w));
            *(float4*)&sz[m * 20 + b4] = make_float4(o0, o1, o2, o3);
        }
        __syncthreads();

        // p4: gates — 1 cell/thread
        {
            float zi = sz[(4 * u + 0) * 20 + bl];
            float zf = sz[(4 * u + 1) * 20 + bl];
            float zg = sz[(4 * u + 2) * 20 + bl];
            float zo = sz[(4 * u + 3) * 20 + bl];
            float ci = sr[bl] ? 0.0f : creg;
            float iv = sig_fast(zi), fv = sig_fast(zf);
            float gv = tanh_fast(zg), ov = sig_fast(zo);
            float nc = fmaf(fv, ci, iv * gv);
            float nh = ov * tanh_fast(nc);
            nc = fminf(1.0f, fmaxf(-1.0f, nc));
            nh = fminf(1.0f, fmaxf(-1.0f, nh));
            creg = nc;
            snh[u * 16 + bl] = nh;
        }
        __syncthreads();

        // p5: write ys (fp32) + h (fp16); thread tid<64: batch bl2, units q*4..+3
        if (tid < 64) {
            int bl2 = tid >> 2, q = tid & 3;
            float v0 = snh[(q * 4 + 0) * 16 + bl2];
            float v1 = snh[(q * 4 + 1) * 16 + bl2];
            float v2 = snh[(q * 4 + 2) * 16 + bl2];
            float v3 = snh[(q * 4 + 3) * 16 + bl2];
            int b = bg * GB + bl2;
            *(float4*)(ys + ((size_t)t * BATCH + b) * HID + cb * 16 + q * 4) =
                make_float4(v0, v1, v2, v3);
            __half h0v = __float2half_rn(v0), h1v = __float2half_rn(v1);
            __half h2v = __float2half_rn(v2), h3v = __float2half_rn(v3);
            uint2 ph;
            ph.x = (uint32_t)__half_as_ushort(h0v) | ((uint32_t)__half_as_ushort(h1v) << 16);
            ph.y = (uint32_t)__half_as_ushort(h2v) | ((uint32_t)__half_as_ushort(h3v) << 16);
            __stcg((uint2*)(g_hb + b * HID + cb * 16 + q * 4), ph);
        }
        __syncthreads();

        // per-group grid barrier (32 CTAs)
        if (tid == 0) {
            unsigned tgt = (unsigned)(t + 1) * (unsigned)CPG;
            asm volatile("red.release.gpu.global.add.u32 [%0], %1;"
                         :: "l"(barp), "r"(1u) : "memory");
            unsigned v;
            do {
                asm volatile("ld.acquire.gpu.global.u32 %0, [%1];"
                             : "=r"(v) : "l"(barp) : "memory");
            } while (v < tgt);
        }
        __syncthreads();
    }
}

// ---------------- launch ----------------
extern "C" void kernel_launch(void* const* d_in, const int* in_sizes, int n_in,
                              void* d_out, int out_size) {
    (void)in_sizes; (void)n_in; (void)out_size;
    const float*         xs     = (const float*)d_in[0];
    const unsigned char* resets = (const unsigned char*)d_in[1];
    const float*         c0     = (const float*)d_in[2];
    const float*         h0     = (const float*)d_in[3];
    const float*         Wi     = (const float*)d_in[4];
    const float*         Wh     = (const float*)d_in[5];
    const float*         bias   = (const float*)d_in[6];
    float*               ys     = (float*)d_out;

    cudaFuncSetAttribute(lstm_kernel,
                         cudaFuncAttributeMaxDynamicSharedMemorySize, SMEM_TOTAL);
    cudaFuncSetAttribute(pregemm_hmma_kernel,
                         cudaFuncAttributeMaxDynamicSharedMemorySize, PSMEM);

    zero_kernel<<<1, 256>>>();
    detect_kernel<<<32, 256>>>(resets);
    init_kernel<<<64, 512>>>(resets, h0);

    dim3 gw(NCOLS / 32, HID / 32);
    wi_prep_kernel<<<gw, 256>>>(Wi);
    x_prep_kernel<<<(T_STEPS * BATCH * HID / 4) / 256, 256>>>(xs);

    dim3 g1(NCOLS / 128, T_STEPS);
    pregemm_hmma_kernel<<<g1, 256, PSMEM>>>(bias);

    lstm_kernel<<<L_CTAS, L_TPB, SMEM_TOTAL>>>(c0, Wh, ys);
}

// round 16
// speedup vs baseline: 2.7360x; 1.0874x over previous
#include <cuda_runtime.h>
#include <cuda_fp16.h>
#include <cstdint>

#define T_STEPS 512
#define BATCH   64
#define HID     512
#define NCOLS   2048

#define L_CTAS  128
#define L_TPB   256
#define NGROUP  4
#define CPG     32       // CTAs per group
#define GB      16       // batches per group

// ---- lstm smem byte offsets ----
#define SA_HI 0                        // A hi: 64 rows x 1024B
#define SA_LO 65536                    // A lo
#define SB    131072                   // B (h fp16): 16 rows x 1024B
#define SPART 147456                   // 2 slabs of 64x20 fp32 (5120B each)
#define SNH   (SPART + 10240)          // 256 floats
#define SR    (SNH + 1024)
#define SMEM_TOTAL (SR + 64)           // 158784

// ---- pregemm smem byte offsets (256B-pitch tiles) ----
#define PA_HI 0
#define PA_LO 32768
#define PB    65536
#define PSMEM 81920

// ---------------- scratch ----------------
__device__ __align__(16) __half g_hb[BATCH * HID];                     // h fp16 [b][k]
__device__ __align__(16) float g_Zx[(size_t)T_STEPS * NCOLS * BATCH];  // [t][prow][b]
__device__ __align__(16) __half g_wih[NCOLS * HID];                    // WiT hi [col][k]
__device__ __align__(16) __half g_wil[NCOLS * HID];                    // WiT lo [col][k]
__device__ __align__(16) __half g_xh[(size_t)T_STEPS * BATCH * HID];   // xs fp16 [t][b][k]
__device__ unsigned int g_barr[NGROUP * 32];
__device__ int g_is_u8;
__device__ unsigned char g_r[T_STEPS * BATCH];

// ---------------- FMA-only activations ----------------
__device__ __forceinline__ float rcp_nr(float v) {
    float y = __int_as_float(0x7EF311C3 - __float_as_int(v));
    y = y * (2.0f - v * y);
    y = y * (2.0f - v * y);
    y = y * (2.0f - v * y);
    return y;
}
__device__ __forceinline__ float sig_fast(float x) {
    float s = fminf(fmaxf(-x * 1.4426950408889634f, -30.0f), 30.0f);
    float fl = floorf(s);
    float f = s - fl;
    float p = 1.5403530393381609e-4f;
    p = fmaf(p, f, 1.3333558146428443e-3f);
    p = fmaf(p, f, 9.6181291076284770e-3f);
    p = fmaf(p, f, 5.5504108664821580e-2f);
    p = fmaf(p, f, 2.4022650695910070e-1f);
    p = fmaf(p, f, 6.9314718055994530e-1f);
    p = fmaf(p, f, 1.0f);
    float uu = __int_as_float(__float_as_int(p) + (((int)fl) << 23));
    return rcp_nr(1.0f + uu);
}
__device__ __forceinline__ float tanh_fast(float x) {
    return fmaf(2.0f, sig_fast(2.0f * x), -1.0f);
}

// swizzled tile offsets (bytes)
__device__ __forceinline__ uint32_t aoff(int m, int k) {      // 1024B pitch
    return (uint32_t)m * 1024u + (((uint32_t)k * 2u) ^ (((uint32_t)m & 7u) << 4));
}

#define MMA16816(d, a, b0v, b1v) \
    asm volatile("mma.sync.aligned.m16n8k16.row.col.f32.f16.f16.f32 " \
        "{%0,%1,%2,%3}, {%4,%5,%6,%7}, {%8,%9}, {%0,%1,%2,%3};" \
        : "+f"((d)[0]), "+f"((d)[1]), "+f"((d)[2]), "+f"((d)[3]) \
        : "r"((a)[0]), "r"((a)[1]), "r"((a)[2]), "r"((a)[3]), "r"(b0v), "r"(b1v))

#define LDSM_X4(r, a) \
    asm volatile("ldmatrix.sync.aligned.m8n8.x4.shared.b16 {%0,%1,%2,%3}, [%4];" \
        : "=r"((r)[0]), "=r"((r)[1]), "=r"((r)[2]), "=r"((r)[3]) : "r"(a))

// ---------------- setup kernels ----------------
__global__ void zero_kernel() {
    int i = threadIdx.x;
    if (i < NGROUP * 32) g_barr[i] = 0u;
    if (i == 0) g_is_u8 = 0;
}

__global__ void detect_kernel(const unsigned char* __restrict__ r) {
    __shared__ int any;
    if (threadIdx.x == 0) any = 0;
    __syncthreads();
    int i = blockIdx.x * blockDim.x + threadIdx.x;
    uchar4 v = ((const uchar4*)r)[i];
    if (v.y | v.z | v.w) any = 1;
    __syncthreads();
    if (threadIdx.x == 0 && any) atomicExch(&g_is_u8, 1);
}

__global__ void init_kernel(const unsigned char* __restrict__ resets,
                            const float* __restrict__ h0) {
    int i = blockIdx.x * blockDim.x + threadIdx.x;
    g_r[i] = g_is_u8 ? (resets[i] != 0) : (((const int*)resets)[i] != 0);
    g_hb[i] = __float2half_rn(h0[i]);
}

__global__ __launch_bounds__(256) void wi_prep_kernel(const float* __restrict__ Wi) {
    __shared__ float tile[32][33];
    int tx = threadIdx.x & 31, ty = threadIdx.x >> 5;
    int c0 = blockIdx.x * 32, k0 = blockIdx.y * 32;
#pragma unroll
    for (int i = 0; i < 4; i++)
        tile[ty + 8 * i][tx] = Wi[(size_t)(k0 + ty + 8 * i) * NCOLS + c0 + tx];
    __syncthreads();
#pragma unroll
    for (int i = 0; i < 4; i++) {
        int cc = ty + 8 * i, kk = tx;
        float w = tile[kk][cc];
        __half hi = __float2half_rn(w);
        __half lo = __float2half_rn(w - __half2float(hi));
        g_wih[(size_t)(c0 + cc) * HID + k0 + kk] = hi;
        g_wil[(size_t)(c0 + cc) * HID + k0 + kk] = lo;
    }
}

__global__ __launch_bounds__(256) void x_prep_kernel(const float* __restrict__ xs) {
    int i4 = blockIdx.x * blockDim.x + threadIdx.x;
    float4 v = ((const float4*)xs)[i4];
    __half2 a = __floats2half2_rn(v.x, v.y);
    __half2 b = __floats2half2_rn(v.z, v.w);
    uint2 o;
    o.x = *(uint32_t*)&a; o.y = *(uint32_t*)&b;
    ((uint2*)g_xh)[i4] = o;
}

// ---------------- HMMA pre-GEMM (LDSM): Zx[t][prow][b] ----------------
__global__ __launch_bounds__(256, 2) void pregemm_hmma_kernel(
    const float* __restrict__ bias)
{
    extern __shared__ char psm[];
    uint32_t sms = (uint32_t)__cvta_generic_to_shared(psm);
    int t = blockIdx.y, cb = blockIdx.x * 128;
    int tid = threadIdx.x, wid = tid >> 5, lane = tid & 31;
    int g = lane >> 2, tg = lane & 3;

    // ldmatrix per-lane geometry (256B pitch)
    int rowA = wid * 16 + ((lane >> 3) & 1) * 8 + (lane & 7);
    uint32_t baseAhi = sms + PA_HI + (uint32_t)rowA * 256u;
    uint32_t baseAlo = sms + PA_LO + (uint32_t)rowA * 256u;
    uint32_t colA = (uint32_t)(lane >> 4) * 16u;
    uint32_t swA = (uint32_t)(rowA & 7) << 4;
    int rBq = (lane >> 4) * 8 + (lane & 7);      // row within 16-row B group
    uint32_t colB = (uint32_t)((lane >> 3) & 1) * 16u;
    uint32_t swB = (uint32_t)(rBq & 7) << 4;

    float d[8][4];
#pragma unroll
    for (int nt = 0; nt < 8; nt++)
#pragma unroll
        for (int e = 0; e < 4; e++) d[nt][e] = 0.0f;

    for (int kc = 0; kc < 4; kc++) {
#pragma unroll
        for (int it = 0; it < 8; it++) {
            int idx = tid + it * 256;
            int r = idx >> 4, ch = idx & 15;
            uint32_t o = (uint32_t)r * 256u + (((uint32_t)ch * 16u) ^ (((uint32_t)r & 7u) << 4));
            *(uint4*)(psm + PA_HI + o) =
                *(const uint4*)(g_wih + (size_t)(cb + r) * HID + kc * 128 + ch * 8);
            *(uint4*)(psm + PA_LO + o) =
                *(const uint4*)(g_wil + (size_t)(cb + r) * HID + kc * 128 + ch * 8);
        }
#pragma unroll
        for (int it = 0; it < 4; it++) {
            int idx = tid + it * 256;
            int n = idx >> 4, ch = idx & 15;
            uint32_t o = (uint32_t)n * 256u + (((uint32_t)ch * 16u) ^ (((uint32_t)n & 7u) << 4));
            *(uint4*)(psm + PB + o) =
                *(const uint4*)(g_xh + ((size_t)t * BATCH + n) * HID + kc * 128 + ch * 8);
        }
        __syncthreads();

#pragma unroll
        for (int k16 = 0; k16 < 8; k16++) {
            uint32_t kb = (uint32_t)k16 * 32u;
            uint32_t ah[4], al[4];
            LDSM_X4(ah, baseAhi + ((kb + colA) ^ swA));
            LDSM_X4(al, baseAlo + ((kb + colA) ^ swA));
#pragma unroll
            for (int q = 0; q < 4; q++) {
                uint32_t bb[4];
                LDSM_X4(bb, sms + PB + (uint32_t)(q * 16 + rBq) * 256u + ((kb + colB) ^ swB));
                MMA16816(d[q * 2 + 0], ah, bb[0], bb[1]);
                MMA16816(d[q * 2 + 0], al, bb[0], bb[1]);
                MMA16816(d[q * 2 + 1], ah, bb[2], bb[3]);
                MMA16816(d[q * 2 + 1], al, bb[2], bb[3]);
            }
        }
        __syncthreads();
    }

    {
        int r0 = wid * 16 + g;
        int col0 = cb + r0, col1 = cb + r0 + 8;
        float bv0 = bias[col0], bv1 = bias[col1];
        int prow0 = (col0 & 511) * 4 + (col0 >> 9);
        int prow1 = (col1 & 511) * 4 + (col1 >> 9);
        float* z0 = g_Zx + ((size_t)t * NCOLS + prow0) * BATCH;
        float* z1 = g_Zx + ((size_t)t * NCOLS + prow1) * BATCH;
#pragma unroll
        for (int nt = 0; nt < 8; nt++) {
            int b = nt * 8 + 2 * tg;
            *(float2*)(z0 + b) = make_float2(d[nt][0] + bv0, d[nt][1] + bv0);
            *(float2*)(z1 + b) = make_float2(d[nt][2] + bv1, d[nt][3] + bv1);
        }
    }
}

// ---------------- persistent HMMA recurrent kernel ----------------
__global__ __launch_bounds__(L_TPB, 1) void lstm_kernel(
    const float* __restrict__ c0, const float* __restrict__ Wh,
    float* __restrict__ ys)
{
    extern __shared__ char smem[];
    uint32_t sms = (uint32_t)__cvta_generic_to_shared(smem);
    float* spf = (float*)(smem + SPART);
    float* sz  = spf;
    float* snh = (float*)(smem + SNH);
    unsigned char* sr = (unsigned char*)(smem + SR);

    int cta = blockIdx.x;
    int bg = cta >> 5;
    int cb = cta & 31;
    int tid = threadIdx.x, wid = tid >> 5, lane = tid & 31;
    int g = lane >> 2, tg = lane & 3;

    // prologue: Wh slice -> fp16 hi/lo
    for (int it = 0; it < 128; it++) {
        int idx = tid + it * 256;
        int m = idx >> 9, k = idx & 511;
        float w = Wh[(size_t)k * NCOLS + (m & 3) * 512 + cb * 16 + (m >> 2)];
        __half hi = __float2half_rn(w);
        __half lo = __float2half_rn(w - __half2float(hi));
        uint32_t o = aoff(m, k);
        *(__half*)(smem + SA_HI + o) = hi;
        *(__half*)(smem + SA_LO + o) = lo;
    }

    int u = tid >> 4, bl = tid & 15;
    float creg = c0[(bg * GB + bl) * HID + cb * 16 + u];

    // MMA roles + ldmatrix geometry (1024B pitch)
    int kh = wid >> 2, mt = wid & 3;
    int m0 = mt * 16 + g;
    int rowA = mt * 16 + ((lane >> 3) & 1) * 8 + (lane & 7);
    uint32_t baseAhi = sms + SA_HI + (uint32_t)rowA * 1024u;
    uint32_t baseAlo = sms + SA_LO + (uint32_t)rowA * 1024u;
    uint32_t colA = (uint32_t)(lane >> 4) * 16u;
    uint32_t swA = (uint32_t)(rowA & 7) << 4;
    int rowB = ((lane >> 4) & 1) * 8 + (lane & 7);
    uint32_t baseB = sms + SB + (uint32_t)rowB * 1024u;
    uint32_t colB = (uint32_t)((lane >> 3) & 1) * 16u;
    uint32_t swB = (uint32_t)(rowB & 7) << 4;

    // p3 mapping (also used for Zx preload)
    int pm = tid >> 2, pb4 = (tid & 3) * 4;
    unsigned int* barp = &g_barr[bg * 32];
    __syncthreads();

    for (int t = 0; t < T_STEPS; t++) {
        // p0: preload Zx for this step (consumed in p3; hides DRAM latency)
        float4 zx = __ldcg((const float4*)(g_Zx +
            ((size_t)t * NCOLS + cb * 64 + pm) * BATCH + bg * GB + pb4));
        if (tid < GB) sr[tid] = g_r[t * BATCH + bg * GB + tid];

        // p1: load group's h rows (16 x 1KB)
#pragma unroll
        for (int it = 0; it < 4; it++) {
            int idx = tid + it * 256;
            int n = idx >> 6, ch = idx & 63;
            uint32_t o = (uint32_t)n * 1024u + (((uint32_t)ch * 16u) ^ (((uint32_t)n & 7u) << 4));
            uint4 v = __ldcg((const uint4*)(g_hb + (bg * GB + n) * HID + ch * 8));
            *(uint4*)(smem + SB + o) = v;
        }
        __syncthreads();

        // p2: MMA via ldmatrix — warp (kh, mt)
        {
            float d[2][4];
#pragma unroll
            for (int nt = 0; nt < 2; nt++)
#pragma unroll
                for (int e = 0; e < 4; e++) d[nt][e] = 0.0f;
#pragma unroll
            for (int j = 0; j < 16; j++) {
                uint32_t kb = (uint32_t)(kh * 16 + j) * 32u;
                uint32_t ah[4], al[4], bb[4];
                LDSM_X4(ah, baseAhi + ((kb + colA) ^ swA));
                LDSM_X4(al, baseAlo + ((kb + colA) ^ swA));
                LDSM_X4(bb, baseB + ((kb + colB) ^ swB));
                MMA16816(d[0], ah, bb[0], bb[1]);
                MMA16816(d[0], al, bb[0], bb[1]);
                MMA16816(d[1], ah, bb[2], bb[3]);
                MMA16816(d[1], al, bb[2], bb[3]);
            }
            float* sp = spf + kh * 1280;
#pragma unroll
            for (int nt = 0; nt < 2; nt++) {
                int cc = nt * 8 + 2 * tg;
                *(float2*)&sp[(m0) * 20 + cc]     = make_float2(d[nt][0], d[nt][1]);
                *(float2*)&sp[(m0 + 8) * 20 + cc] = make_float2(d[nt][2], d[nt][3]);
            }
        }
        __syncthreads();

        // p3: reduce 2 slabs + preloaded Zx + reset mask -> sz
        {
            float4 p0 = *(const float4*)&spf[pm * 20 + pb4];
            float4 p1 = *(const float4*)&spf[1280 + pm * 20 + pb4];
            float o0 = zx.x + (sr[pb4 + 0] ? 0.f : (p0.x + p1.x));
            float o1 = zx.y + (sr[pb4 + 1] ? 0.f : (p0.y + p1.y));
            float o2 = zx.z + (sr[pb4 + 2] ? 0.f : (p0.z + p1.z));
            float o3 = zx.w + (sr[pb4 + 3] ? 0.f : (p0.w + p1.w));
            *(float4*)&sz[pm * 20 + pb4] = make_float4(o0, o1, o2, o3);
        }
        __syncthreads();

        // p4: gates — 1 cell/thread
        {
            float zi = sz[(4 * u + 0) * 20 + bl];
            float zf = sz[(4 * u + 1) * 20 + bl];
            float zg = sz[(4 * u + 2) * 20 + bl];
            float zo = sz[(4 * u + 3) * 20 + bl];
            float ci = sr[bl] ? 0.0f : creg;
            float iv = sig_fast(zi), fv = sig_fast(zf);
            float gv = tanh_fast(zg), ov = sig_fast(zo);
            float nc = fmaf(fv, ci, iv * gv);
            float nh = ov * tanh_fast(nc);
            nc = fminf(1.0f, fmaxf(-1.0f, nc));
            nh = fminf(1.0f, fmaxf(-1.0f, nh));
            creg = nc;
            snh[u * 16 + bl] = nh;
        }
        __syncthreads();

        // p5: write ys (fp32) + h (fp16)
        if (tid < 64) {
            int bl2 = tid >> 2, q = tid & 3;
            float v0 = snh[(q * 4 + 0) * 16 + bl2];
            float v1 = snh[(q * 4 + 1) * 16 + bl2];
            float v2 = snh[(q * 4 + 2) * 16 + bl2];
            float v3 = snh[(q * 4 + 3) * 16 + bl2];
            int b = bg * GB + bl2;
            *(float4*)(ys + ((size_t)t * BATCH + b) * HID + cb * 16 + q * 4) =
                make_float4(v0, v1, v2, v3);
            __half h0v = __float2half_rn(v0), h1v = __float2half_rn(v1);
            __half h2v = __float2half_rn(v2), h3v = __float2half_rn(v3);
            uint2 ph;
            ph.x = (uint32_t)__half_as_ushort(h0v) | ((uint32_t)__half_as_ushort(h1v) << 16);
            ph.y = (uint32_t)__half_as_ushort(h2v) | ((uint32_t)__half_as_ushort(h3v) << 16);
            __stcg((uint2*)(g_hb + b * HID + cb * 16 + q * 4), ph);
        }
        __syncthreads();

        // per-group grid barrier (32 CTAs)
        if (tid == 0) {
            unsigned tgt = (unsigned)(t + 1) * (unsigned)CPG;
            asm volatile("red.release.gpu.global.add.u32 [%0], %1;"
                         :: "l"(barp), "r"(1u) : "memory");
            unsigned v;
            do {
                asm volatile("ld.acquire.gpu.global.u32 %0, [%1];"
                             : "=r"(v) : "l"(barp) : "memory");
            } while (v < tgt);
        }
        __syncthreads();
    }
}

// ---------------- launch ----------------
extern "C" void kernel_launch(void* const* d_in, const int* in_sizes, int n_in,
                              void* d_out, int out_size) {
    (void)in_sizes; (void)n_in; (void)out_size;
    const float*         xs     = (const float*)d_in[0];
    const unsigned char* resets = (const unsigned char*)d_in[1];
    const float*         c0     = (const float*)d_in[2];
    const float*         h0     = (const float*)d_in[3];
    const float*         Wi     = (const float*)d_in[4];
    const float*         Wh     = (const float*)d_in[5];
    const float*         bias   = (const float*)d_in[6];
    float*               ys     = (float*)d_out;

    cudaFuncSetAttribute(lstm_kernel,
                         cudaFuncAttributeMaxDynamicSharedMemorySize, SMEM_TOTAL);
    cudaFuncSetAttribute(pregemm_hmma_kernel,
                         cudaFuncAttributeMaxDynamicSharedMemorySize, PSMEM);

    zero_kernel<<<1, 256>>>();
    detect_kernel<<<32, 256>>>(resets);
    init_kernel<<<64, 512>>>(resets, h0);

    dim3 gw(NCOLS / 32, HID / 32);
    wi_prep_kernel<<<gw, 256>>>(Wi);
    x_prep_kernel<<<(T_STEPS * BATCH * HID / 4) / 256, 256>>>(xs);

    dim3 g1(NCOLS / 128, T_STEPS);
    pregemm_hmma_kernel<<<g1, 256, PSMEM>>>(bias);

    lstm_kernel<<<L_CTAS, L_TPB, SMEM_TOTAL>>>(c0, Wh, ys);
}